// round 2
// baseline (speedup 1.0000x reference)
#include <cuda_runtime.h>
#include <math.h>

#define NQ   10
#define KDIM 4096
#define NDIM 1024
#define BM   128
#define BN   128
#define BK   16

// out[m][e] = sum_f relu( sum_j q[m][j]*W1[f][j] ) * W2[e][f]
// q[m][0]   = prod_{i=1..9} cos(x[m][i]+qp[i])
// q[m][k]   = prod_{i=0..k} cos(x[m][i]+qp[i]),  k>=1
__global__ __launch_bounds__(256)
void ffq_fused_kernel(const float* __restrict__ x,
                      const float* __restrict__ qp,
                      const float* __restrict__ W1,
                      const float* __restrict__ W2,
                      float* __restrict__ out)
{
    __shared__ float qs[BM][NQ];      // per-row quantum features
    __shared__ float As[BK][BM];      // h tile (k-major)
    __shared__ float Bs[BK][BN];      // W2 tile (k-major)

    const int tid = threadIdx.x;
    const int bm  = blockIdx.y * BM;
    const int bn  = blockIdx.x * BN;

    // ---- Phase 0: analytic quantum sim for this block's 128 rows ----
    if (tid < BM) {
        const int r = bm + tid;
        float c[NQ];
#pragma unroll
        for (int j = 0; j < NQ; j++)
            c[j] = cosf(x[r * NQ + j] + qp[j]);
        float suf = 1.0f;
#pragma unroll
        for (int j = 1; j < NQ; j++) suf *= c[j];
        qs[tid][0] = suf;                 // wire 0: product of c[1..9]
        float pre = c[0];
#pragma unroll
        for (int j = 1; j < NQ; j++) { pre *= c[j]; qs[tid][j] = pre; }
    }
    __syncthreads();

    // thread -> 8x8 microtile
    const int ty = tid >> 4;          // 0..15  (m direction)
    const int tx = tid & 15;          // 0..15  (n direction)

    // A-tile builder assignment: each thread owns one m-row, 8 k's.
    const int a_m  = tid >> 1;        // 0..127
    const int a_kh = (tid & 1) * 8;   // 0 or 8

    float acc[8][8];
#pragma unroll
    for (int i = 0; i < 8; i++)
#pragma unroll
        for (int j = 0; j < 8; j++) acc[i][j] = 0.0f;

    // cache this thread's q row in registers (conflict-free: 16 consecutive m,
    // stride-10-word rows span 16 distinct banks; thread pairs broadcast)
    float qr[NQ];
#pragma unroll
    for (int j = 0; j < NQ; j++) qr[j] = qs[a_m][j];

    for (int kk = 0; kk < KDIM; kk += BK) {
        // ---- build As[k][m] = relu(q . W1[kk+k]) on the fly ----
#pragma unroll
        for (int ki = 0; ki < 8; ki++) {
            const int k = a_kh + ki;
            const float* w = &W1[(kk + k) * NQ];
            float s = 0.0f;
#pragma unroll
            for (int j = 0; j < NQ; j++) s += qr[j] * w[j];   // W1 row broadcast via L1
            As[k][a_m] = fmaxf(s, 0.0f);
        }

        // ---- load Bs from W2 (row-major [NDIM][KDIM], K contiguous) ----
#pragma unroll
        for (int v = 0; v < 2; v++) {
            const int idx  = tid + v * 256;      // 0..511 float4 ids
            const int nrow = idx >> 2;           // 0..127
            const int kc   = (idx & 3) * 4;      // 0,4,8,12
            const float4 t = *(const float4*)&W2[(size_t)(bn + nrow) * KDIM + kk + kc];
            Bs[kc + 0][nrow] = t.x;
            Bs[kc + 1][nrow] = t.y;
            Bs[kc + 2][nrow] = t.z;
            Bs[kc + 3][nrow] = t.w;
        }
        __syncthreads();

        // ---- 128x128x16 FFMA block ----
#pragma unroll
        for (int k = 0; k < BK; k++) {
            float a[8], b[8];
            const float4 a0 = *(const float4*)&As[k][ty * 8];
            const float4 a1 = *(const float4*)&As[k][ty * 8 + 4];
            const float4 b0 = *(const float4*)&Bs[k][tx * 8];
            const float4 b1 = *(const float4*)&Bs[k][tx * 8 + 4];
            a[0]=a0.x; a[1]=a0.y; a[2]=a0.z; a[3]=a0.w;
            a[4]=a1.x; a[5]=a1.y; a[6]=a1.z; a[7]=a1.w;
            b[0]=b0.x; b[1]=b0.y; b[2]=b0.z; b[3]=b0.w;
            b[4]=b1.x; b[5]=b1.y; b[6]=b1.z; b[7]=b1.w;
#pragma unroll
            for (int i = 0; i < 8; i++)
#pragma unroll
                for (int j = 0; j < 8; j++)
                    acc[i][j] += a[i] * b[j];
        }
        __syncthreads();
    }

    // ---- epilogue: float4 stores ----
#pragma unroll
    for (int i = 0; i < 8; i++) {
        const int m = bm + ty * 8 + i;
        float* o = &out[(size_t)m * NDIM + bn + tx * 8];
        *(float4*)&o[0] = make_float4(acc[i][0], acc[i][1], acc[i][2], acc[i][3]);
        *(float4*)&o[4] = make_float4(acc[i][4], acc[i][5], acc[i][6], acc[i][7]);
    }
}

extern "C" void kernel_launch(void* const* d_in, const int* in_sizes, int n_in,
                              void* d_out, int out_size)
{
    const float* x   = (const float*)d_in[0];   // [B*S, 10]
    const float* qp  = (const float*)d_in[1];   // [10]
    const float* W1  = (const float*)d_in[2];   // [4096, 10]
    const float* W2  = (const float*)d_in[3];   // [1024, 4096]
    float* out = (float*)d_out;                 // [B*S, 1024]

    const int M = in_sizes[0] / NQ;             // 16384

    dim3 grid(NDIM / BN, M / BM);               // (8, 128)
    ffq_fused_kernel<<<grid, 256>>>(x, qp, W1, W2, out);
}

// round 4
// speedup vs baseline: 4.4762x; 4.4762x over previous
#include <cuda_runtime.h>
#include <cuda_bf16.h>
#include <math.h>
#include <stdint.h>

typedef unsigned long long ull;

#define NQ      10
#define KDIM    4096
#define NDIM    1024

// ---- feature guard: tcgen05 only exists in the sm_103a ('a'-feature) pass ----
#if defined(__CUDA_ARCH__) && defined(__CUDA_ARCH_HAS_FEATURE__)
#  if __CUDA_ARCH_HAS_FEATURE__(SM103_ALL) || __CUDA_ARCH_HAS_FEATURE__(SM100_ALL)
#    define TC_OK 1
#  endif
#endif
#ifndef TC_OK
#  define TC_OK 0
#endif

// ============================================================================
// Kernel A: tcgen05 bf16 hi/lo-split GEMM (active only when SM103_ALL)
// ============================================================================
#define BM      256
#define BN      256
#define KC      64
#define NCHUNK  (KDIM / KC)          // 64
#define THREADS 256

#define OFF_TMEM 0
#define OFF_MBAR 16
#define OFF_W1   64
#define OFF_A    4096                // [buf][tile][hi/lo] 8 x 16KB = 128KB
#define OFF_B    135168              // [hi/lo] 2 x 32KB
#define SMEM_BYTES 200704
#define A_TILE_BYTES 16384
#define B_PART_BYTES 32768

// idesc kind::f16: dtype=F32, a/b=BF16, N=256, M=128
#define IDESC 0x08400490u

#define SW128(o) ((o) ^ (((o) >> 3) & 0x70))

#if TC_OK
static __device__ __forceinline__ uint32_t smem_u32(const void* p) {
    uint32_t a;
    asm("{ .reg .u64 t; cvta.to.shared.u64 t, %1; cvt.u32.u64 %0, t; }" : "=r"(a) : "l"(p));
    return a;
}
static __device__ __forceinline__ bool elect_one() {
    uint32_t p;
    asm volatile("{ .reg .pred P; elect.sync _|P, 0xFFFFFFFF; selp.b32 %0, 1, 0, P; }" : "=r"(p));
    return p != 0;
}
static __device__ __forceinline__ ull make_desc(uint32_t addr) {  // SW128, K-major
    return (2ULL << 61) | (1ULL << 46) | (64ULL << 32) | (1ULL << 16) |
           (ull)((addr >> 4) & 0x3FFF);
}
static __device__ __forceinline__ ull fma2(ull a, ull b, ull c) {
    ull d;
    asm("fma.rn.f32x2 %0, %1, %2, %3;" : "=l"(d) : "l"(a), "l"(b), "l"(c));
    return d;
}
static __device__ __forceinline__ uint32_t pack_bf16(float lo, float hi) {
    uint32_t r;
    asm("cvt.rn.bf16x2.f32 %0, %1, %2;" : "=r"(r) : "f"(hi), "f"(lo));
    return r;
}
static __device__ __forceinline__ void cvt_split(float x0, float x1, uint32_t& h, uint32_t& l) {
    h = pack_bf16(x0, x1);
    float h0 = __uint_as_float(h << 16);
    float h1 = __uint_as_float(h & 0xFFFF0000u);
    l = pack_bf16(x0 - h0, x1 - h1);
}
static __device__ __forceinline__ void sts128(uint32_t a, uint32_t x, uint32_t y, uint32_t z, uint32_t w) {
    asm volatile("st.shared.v4.b32 [%0], {%1,%2,%3,%4};" :: "r"(a), "r"(x), "r"(y), "r"(z), "r"(w) : "memory");
}
static __device__ __forceinline__ void mbar_wait(uint32_t mbar, uint32_t ph) {
    asm volatile(
        "{\n\t.reg .pred P;\n"
        "WL_%=:\n\t"
        "mbarrier.try_wait.parity.acquire.cta.shared::cta.b64 P, [%0], %1, 0x989680;\n\t"
        "@P bra WD_%=;\n\t"
        "bra WL_%=;\n"
        "WD_%=:\n\t}"
        :: "r"(mbar), "r"(ph) : "memory");
}
static __device__ __forceinline__ void mma_ss(uint32_t d, ull a, ull b, uint32_t en) {
    asm volatile(
        "{\n\t.reg .pred p;\n\t"
        "setp.ne.u32 p, %5, 0;\n\t"
        "tcgen05.mma.cta_group::1.kind::f16 [%0], %1, %2, %3, {%4,%4,%4,%4}, p;\n\t}"
        :: "r"(d), "l"(a), "l"(b), "r"(IDESC), "r"(0u), "r"(en) : "memory");
}

#define LDTM32(r, addr) asm volatile( \
    "tcgen05.ld.sync.aligned.32x32b.x32.b32 " \
    "{%0,%1,%2,%3,%4,%5,%6,%7,%8,%9,%10,%11,%12,%13,%14,%15," \
    "%16,%17,%18,%19,%20,%21,%22,%23,%24,%25,%26,%27,%28,%29,%30,%31}, [%32];" \
    : "=r"(r[0]),"=r"(r[1]),"=r"(r[2]),"=r"(r[3]),"=r"(r[4]),"=r"(r[5]),"=r"(r[6]),"=r"(r[7]), \
      "=r"(r[8]),"=r"(r[9]),"=r"(r[10]),"=r"(r[11]),"=r"(r[12]),"=r"(r[13]),"=r"(r[14]),"=r"(r[15]), \
      "=r"(r[16]),"=r"(r[17]),"=r"(r[18]),"=r"(r[19]),"=r"(r[20]),"=r"(r[21]),"=r"(r[22]),"=r"(r[23]), \
      "=r"(r[24]),"=r"(r[25]),"=r"(r[26]),"=r"(r[27]),"=r"(r[28]),"=r"(r[29]),"=r"(r[30]),"=r"(r[31]) \
    : "r"(addr))
#endif  // TC_OK

__global__ __launch_bounds__(THREADS, 1)
void ffq_tc_kernel(const float* __restrict__ x,
                   const float* __restrict__ qp,
                   const float* __restrict__ W1,
                   const float* __restrict__ W2,
                   float* __restrict__ out)
{
#if TC_OK
    extern __shared__ char smem[];
    const uint32_t sbase = smem_u32(smem);
    const int tid = threadIdx.x;
    const int bm = blockIdx.y * BM;
    const int bn = blockIdx.x * BN;

    if (tid < 32) {
        asm volatile("tcgen05.alloc.cta_group::1.sync.aligned.shared::cta.b32 [%0], %1;"
                     :: "r"(sbase + OFF_TMEM), "r"(512) : "memory");
        asm volatile("tcgen05.relinquish_alloc_permit.cta_group::1.sync.aligned;");
    }
    if (tid == 0) {
        asm volatile("mbarrier.init.shared.b64 [%0], %1;" :: "r"(sbase + OFF_MBAR), "r"(1u) : "memory");
        asm volatile("mbarrier.init.shared.b64 [%0], %1;" :: "r"(sbase + OFF_MBAR + 8), "r"(1u) : "memory");
    }

    // ---- per-thread analytic quantum features: m = bm + tid ----
    ull qq[10];
    {
        const int m = bm + tid;
        float c[NQ];
#pragma unroll
        for (int j = 0; j < NQ; j++) c[j] = cosf(x[m * NQ + j] + qp[j]);
        float suf = 1.0f;
#pragma unroll
        for (int j = 1; j < NQ; j++) suf *= c[j];
        float qv[NQ];
        qv[0] = suf;
        float pre = c[0];
#pragma unroll
        for (int j = 1; j < NQ; j++) { pre *= c[j]; qv[j] = pre; }
#pragma unroll
        for (int j = 0; j < NQ; j++) {
            uint32_t b = __float_as_uint(qv[j]);
            qq[j] = ((ull)b << 32) | (ull)b;
        }
    }

    // ---- prefetch B chunk 0 + stage W1 chunk 0 ----
    const float4* w2row = (const float4*)(W2 + (size_t)(bn + tid) * KDIM);
    float4 f[16];
#pragma unroll
    for (int i = 0; i < 16; i++) f[i] = __ldg(&w2row[i]);

    for (int i = tid; i < KC * NQ; i += THREADS) {
        int k = i / NQ, j = i % NQ;
        *(float*)(smem + OFF_W1 + (k >> 1) * 80 + j * 8 + (k & 1) * 4) = W1[k * NQ + j];
    }
    __syncthreads();

    uint32_t tmem_base;
    asm volatile("ld.shared.b32 %0, [%1];" : "=r"(tmem_base) : "r"(sbase + OFF_TMEM));

    const int at = tid >> 7;          // A tile (0 or 1)
    const int mr = tid & 127;
    const ulonglong2* w1v = (const ulonglong2*)(smem + OFF_W1);

    // ---- produce A for chunk 0 into buffer 0 ----
    {
        const uint32_t ab = sbase + OFF_A + (at * 2) * A_TILE_BYTES;
#pragma unroll
        for (int g = 0; g < 8; ++g) {
            uint32_t wh[4], wl[4];
#pragma unroll
            for (int qi = 0; qi < 4; ++qi) {
                const int kp = g * 4 + qi;
                ull acc = 0ULL;
#pragma unroll
                for (int i = 0; i < 5; i++) {
                    ulonglong2 w = w1v[kp * 5 + i];
                    acc = fma2(qq[2 * i], w.x, acc);
                    acc = fma2(qq[2 * i + 1], w.y, acc);
                }
                float s0 = fmaxf(__uint_as_float((uint32_t)acc), 0.0f);
                float s1 = fmaxf(__uint_as_float((uint32_t)(acc >> 32)), 0.0f);
                cvt_split(s0, s1, wh[qi], wl[qi]);
            }
            const uint32_t sw = SW128(mr * 128 + g * 16);
            sts128(ab + sw, wh[0], wh[1], wh[2], wh[3]);
            sts128(ab + A_TILE_BYTES + sw, wl[0], wl[1], wl[2], wl[3]);
        }
    }

    int ph0 = 0, ph1 = 0;

    for (int c = 0; c < NCHUNK; ++c) {
        const int buf = c & 1;

        if (c > 0) {
            if (buf == 0) { mbar_wait(sbase + OFF_MBAR + 8, ph1); ph1 ^= 1; }
            else          { mbar_wait(sbase + OFF_MBAR,     ph0); ph0 ^= 1; }
        }

        // ---- B convert + STS (from prefetched regs) ----
        {
            const uint32_t bhb = sbase + OFF_B;
#pragma unroll
            for (int g = 0; g < 8; ++g) {
                float4 u = f[2 * g], v = f[2 * g + 1];
                uint32_t h0, h1, h2, h3, l0, l1, l2, l3;
                cvt_split(u.x, u.y, h0, l0);
                cvt_split(u.z, u.w, h1, l1);
                cvt_split(v.x, v.y, h2, l2);
                cvt_split(v.z, v.w, h3, l3);
                const uint32_t sw = SW128(tid * 128 + g * 16);
                sts128(bhb + sw, h0, h1, h2, h3);
                sts128(bhb + B_PART_BYTES + sw, l0, l1, l2, l3);
            }
        }
        asm volatile("fence.proxy.async.shared::cta;" ::: "memory");
        __syncthreads();

        // ---- 24 MMAs + commit ----
        if (tid < 32 && elect_one()) {
            const ull bH = make_desc(sbase + OFF_B);
            const ull bL = make_desc(sbase + OFF_B + B_PART_BYTES);
#pragma unroll
            for (int t = 0; t < 2; ++t) {
                const uint32_t d = tmem_base + t * 256;
                const ull aH = make_desc(sbase + OFF_A + (buf * 4 + t * 2) * A_TILE_BYTES);
                const ull aL = aH + (A_TILE_BYTES >> 4);
#pragma unroll
                for (int ks = 0; ks < 4; ++ks)
                    mma_ss(d, aH + ks * 2, bH + ks * 2, (c > 0) || (ks > 0));
#pragma unroll
                for (int ks = 0; ks < 4; ++ks) mma_ss(d, aL + ks * 2, bH + ks * 2, 1u);
#pragma unroll
                for (int ks = 0; ks < 4; ++ks) mma_ss(d, aH + ks * 2, bL + ks * 2, 1u);
            }
            asm volatile("tcgen05.commit.cta_group::1.mbarrier::arrive::one.shared::cluster.b64 [%0];"
                         :: "r"(sbase + OFF_MBAR + buf * 8) : "memory");
        }

        if (c < NCHUNK - 1) {
#pragma unroll
            for (int i = 0; i < 16; i++) f[i] = __ldg(&w2row[(c + 1) * 16 + i]);
            for (int i = tid; i < KC * NQ; i += THREADS) {
                int k = i / NQ, j = i % NQ;
                *(float*)(smem + OFF_W1 + (k >> 1) * 80 + j * 8 + (k & 1) * 4) =
                    W1[((c + 1) * KC + k) * NQ + j];
            }
            __syncthreads();
            const uint32_t ab = sbase + OFF_A + ((1 - buf) * 4 + at * 2) * A_TILE_BYTES;
#pragma unroll
            for (int g = 0; g < 8; ++g) {
                uint32_t wh[4], wl[4];
#pragma unroll
                for (int qi = 0; qi < 4; ++qi) {
                    const int kp = g * 4 + qi;
                    ull acc = 0ULL;
#pragma unroll
                    for (int i = 0; i < 5; i++) {
                        ulonglong2 w = w1v[kp * 5 + i];
                        acc = fma2(qq[2 * i], w.x, acc);
                        acc = fma2(qq[2 * i + 1], w.y, acc);
                    }
                    float s0 = fmaxf(__uint_as_float((uint32_t)acc), 0.0f);
                    float s1 = fmaxf(__uint_as_float((uint32_t)(acc >> 32)), 0.0f);
                    cvt_split(s0, s1, wh[qi], wl[qi]);
                }
                const uint32_t sw = SW128(mr * 128 + g * 16);
                sts128(ab + sw, wh[0], wh[1], wh[2], wh[3]);
                sts128(ab + A_TILE_BYTES + sw, wl[0], wl[1], wl[2], wl[3]);
            }
        }
    }

    mbar_wait(sbase + OFF_MBAR + 8, ph1);
    asm volatile("tcgen05.fence::after_thread_sync;" ::: "memory");

    // ---- epilogue: TMEM -> GMEM ----
    {
        const int w = tid >> 5, l = tid & 31;
        const int t = w >> 2, sp = w & 3;
        const int m = bm + t * 128 + sp * 32 + l;
        float* orow = out + (size_t)m * NDIM + bn;
#pragma unroll
        for (int cc = 0; cc < 4; ++cc) {
            uint32_t r[64];
            LDTM32(r, tmem_base + t * 256 + cc * 64);
            LDTM32((r + 32), tmem_base + t * 256 + cc * 64 + 32);
            asm volatile("tcgen05.wait::ld.sync.aligned;" ::: "memory");
#pragma unroll
            for (int i = 0; i < 16; ++i) {
                float4 v = make_float4(__uint_as_float(r[4 * i]), __uint_as_float(r[4 * i + 1]),
                                       __uint_as_float(r[4 * i + 2]), __uint_as_float(r[4 * i + 3]));
                *(float4*)(orow + cc * 64 + 4 * i) = v;
            }
        }
    }

    __syncthreads();
    if (tid < 32) {
        asm volatile("tcgen05.dealloc.cta_group::1.sync.aligned.b32 %0, %1;"
                     :: "r"(tmem_base), "r"(512));
    }
#endif  // TC_OK
}

// ============================================================================
// Kernel B: known-good FFMA fallback (round 2) — active only WITHOUT SM103_ALL
// ============================================================================
#define FBM   128
#define FBN   128
#define FBK   16

__global__ __launch_bounds__(256)
void ffq_fused_kernel(const float* __restrict__ x,
                      const float* __restrict__ qp,
                      const float* __restrict__ W1,
                      const float* __restrict__ W2,
                      float* __restrict__ out)
{
#if !TC_OK
    __shared__ float qs[FBM][NQ];
    __shared__ float As[FBK][FBM];
    __shared__ float Bs[FBK][FBN];

    const int tid = threadIdx.x;
    const int bm  = blockIdx.y * FBM;
    const int bn  = blockIdx.x * FBN;

    if (tid < FBM) {
        const int r = bm + tid;
        float c[NQ];
#pragma unroll
        for (int j = 0; j < NQ; j++)
            c[j] = cosf(x[r * NQ + j] + qp[j]);
        float suf = 1.0f;
#pragma unroll
        for (int j = 1; j < NQ; j++) suf *= c[j];
        qs[tid][0] = suf;
        float pre = c[0];
#pragma unroll
        for (int j = 1; j < NQ; j++) { pre *= c[j]; qs[tid][j] = pre; }
    }
    __syncthreads();

    const int ty = tid >> 4;
    const int tx = tid & 15;
    const int a_m  = tid >> 1;
    const int a_kh = (tid & 1) * 8;

    float acc[8][8];
#pragma unroll
    for (int i = 0; i < 8; i++)
#pragma unroll
        for (int j = 0; j < 8; j++) acc[i][j] = 0.0f;

    float qr[NQ];
#pragma unroll
    for (int j = 0; j < NQ; j++) qr[j] = qs[a_m][j];

    for (int kk = 0; kk < KDIM; kk += FBK) {
#pragma unroll
        for (int ki = 0; ki < 8; ki++) {
            const int k = a_kh + ki;
            const float* w = &W1[(kk + k) * NQ];
            float s = 0.0f;
#pragma unroll
            for (int j = 0; j < NQ; j++) s += qr[j] * w[j];
            As[k][a_m] = fmaxf(s, 0.0f);
        }
#pragma unroll
        for (int v = 0; v < 2; v++) {
            const int idx  = tid + v * 256;
            const int nrow = idx >> 2;
            const int kc   = (idx & 3) * 4;
            const float4 t = *(const float4*)&W2[(size_t)(bn + nrow) * KDIM + kk + kc];
            Bs[kc + 0][nrow] = t.x;
            Bs[kc + 1][nrow] = t.y;
            Bs[kc + 2][nrow] = t.z;
            Bs[kc + 3][nrow] = t.w;
        }
        __syncthreads();

#pragma unroll
        for (int k = 0; k < FBK; k++) {
            float a[8], b[8];
            const float4 a0 = *(const float4*)&As[k][ty * 8];
            const float4 a1 = *(const float4*)&As[k][ty * 8 + 4];
            const float4 b0 = *(const float4*)&Bs[k][tx * 8];
            const float4 b1 = *(const float4*)&Bs[k][tx * 8 + 4];
            a[0]=a0.x; a[1]=a0.y; a[2]=a0.z; a[3]=a0.w;
            a[4]=a1.x; a[5]=a1.y; a[6]=a1.z; a[7]=a1.w;
            b[0]=b0.x; b[1]=b0.y; b[2]=b0.z; b[3]=b0.w;
            b[4]=b1.x; b[5]=b1.y; b[6]=b1.z; b[7]=b1.w;
#pragma unroll
            for (int i = 0; i < 8; i++)
#pragma unroll
                for (int j = 0; j < 8; j++)
                    acc[i][j] += a[i] * b[j];
        }
        __syncthreads();
    }

#pragma unroll
    for (int i = 0; i < 8; i++) {
        const int m = bm + ty * 8 + i;
        float* o = &out[(size_t)m * NDIM + bn + tx * 8];
        *(float4*)&o[0] = make_float4(acc[i][0], acc[i][1], acc[i][2], acc[i][3]);
        *(float4*)&o[4] = make_float4(acc[i][4], acc[i][5], acc[i][6], acc[i][7]);
    }
#endif  // !TC_OK
}

extern "C" void kernel_launch(void* const* d_in, const int* in_sizes, int n_in,
                              void* d_out, int out_size)
{
    const float* x  = (const float*)d_in[0];
    const float* qp = (const float*)d_in[1];
    const float* W1 = (const float*)d_in[2];
    const float* W2 = (const float*)d_in[3];
    float* out = (float*)d_out;

    const int M = in_sizes[0] / NQ;   // 16384

    // tcgen05 path (no-op if the loaded SASS lacks the 'a' feature)
    cudaFuncSetAttribute(ffq_tc_kernel, cudaFuncAttributeMaxDynamicSharedMemorySize, SMEM_BYTES);
    dim3 gridA(NDIM / BN, M / BM);    // (4, 64)
    ffq_tc_kernel<<<gridA, THREADS, SMEM_BYTES>>>(x, qp, W1, W2, out);

    // FFMA fallback (no-op when the tcgen05 variant is the loaded SASS)
    dim3 gridB(NDIM / FBN, M / FBM);  // (8, 128)
    ffq_fused_kernel<<<gridB, 256>>>(x, qp, W1, W2, out);
}

// round 5
// speedup vs baseline: 6.1437x; 1.3725x over previous
#include <cuda_runtime.h>
#include <cuda_bf16.h>
#include <math.h>
#include <stdint.h>

typedef unsigned long long ull;

#define NQ      10
#define KDIM    4096
#define NDIM    1024
#define BM      128
#define BN      256
#define KC      64
#define NCHUNK  64
#define THREADS 256
#define NBLK    (NDIM / BN)          // 4

// ---- feature guard: tcgen05 only in the sm_103a pass ----
#if defined(__CUDA_ARCH__) && defined(__CUDA_ARCH_HAS_FEATURE__)
#  if __CUDA_ARCH_HAS_FEATURE__(SM103_ALL) || __CUDA_ARCH_HAS_FEATURE__(SM100_ALL)
#    define TC_OK 1
#  endif
#endif
#ifndef TC_OK
#  define TC_OK 0
#endif

// SMEM layout
#define OFF_TMEM 0
#define OFF_MMA  16                  // 2 x 8B mma-done mbarriers
#define OFF_BF   32                  // 3 x 8B b-full mbarriers
#define OFF_W1   64                  // 2 x 2560B W1 staging
#define OFF_B    8192                // 3 slots x 64KB (hi 32KB | lo 32KB)
#define B_SLOT   65536
#define SMEM_BYTES (OFF_B + 3 * B_SLOT)   // 204800

// idesc kind::f16: dtype=F32, a/b=BF16, M=128, N=256
#define IDESC 0x08400490u

#define SW128(o) ((o) ^ (((o) >> 3) & 0x70))

// converted W2: [nb][chunk][hi 32KB | lo 32KB] pre-swizzled tile images (16MB)
__device__ __align__(1024) unsigned char g_w2conv[(size_t)NBLK * NCHUNK * B_SLOT];

// ---- helpers usable in every pass ----
static __device__ __forceinline__ uint32_t pack_bf16(float lo, float hi) {
    uint32_t r;
    asm("cvt.rn.bf16x2.f32 %0, %1, %2;" : "=r"(r) : "f"(hi), "f"(lo));
    return r;
}
static __device__ __forceinline__ void cvt_split(float x0, float x1, uint32_t& h, uint32_t& l) {
    h = pack_bf16(x0, x1);
    float h0 = __uint_as_float(h << 16);
    float h1 = __uint_as_float(h & 0xFFFF0000u);
    l = pack_bf16(x0 - h0, x1 - h1);
}

// ============================================================================
// Kernel 0: W2 fp32 -> bf16 hi/lo, SW128-swizzled tile images (runs every call)
// ============================================================================
__global__ __launch_bounds__(256)
void convert_w2_kernel(const float* __restrict__ W2)
{
    const int t   = blockIdx.x * 256 + threadIdx.x;   // 0 .. 1024*512-1
    const int row = t >> 9;                           // W2 output row (0..1023)
    const int k0  = (t & 511) << 3;                   // k octet start
    const int nb  = row >> 8, n = row & 255;
    const int c   = k0 >> 6,  k = k0 & 63;

    const float4* p = (const float4*)(W2 + (size_t)row * KDIM + k0);
    const float4 u = p[0], v = p[1];
    uint32_t h0, h1, h2, h3, l0, l1, l2, l3;
    cvt_split(u.x, u.y, h0, l0);
    cvt_split(u.z, u.w, h1, l1);
    cvt_split(v.x, v.y, h2, l2);
    cvt_split(v.z, v.w, h3, l3);

    unsigned char* base = g_w2conv + ((size_t)(nb * NCHUNK + c)) * B_SLOT;
    const uint32_t off = SW128((uint32_t)(n * 128 + k * 2));
    *(uint4*)(base + off)         = make_uint4(h0, h1, h2, h3);
    *(uint4*)(base + 32768 + off) = make_uint4(l0, l1, l2, l3);
}

// ============================================================================
// Kernel A: TS-mode tcgen05 GEMM (A in TMEM, B bulk-copied pre-converted bf16)
// ============================================================================
#if TC_OK
static __device__ __forceinline__ uint32_t smem_u32(const void* p) {
    uint32_t a;
    asm("{ .reg .u64 t; cvta.to.shared.u64 t, %1; cvt.u32.u64 %0, t; }" : "=r"(a) : "l"(p));
    return a;
}
static __device__ __forceinline__ bool elect_one() {
    uint32_t p;
    asm volatile("{ .reg .pred P; elect.sync _|P, 0xFFFFFFFF; selp.b32 %0, 1, 0, P; }" : "=r"(p));
    return p != 0;
}
static __device__ __forceinline__ ull make_desc(uint32_t addr) {  // SW128 K-major
    return (2ULL << 61) | (1ULL << 46) | (64ULL << 32) | (1ULL << 16) |
           (ull)((addr >> 4) & 0x3FFF);
}
static __device__ __forceinline__ ull fma2(ull a, ull b, ull c) {
    ull d;
    asm("fma.rn.f32x2 %0, %1, %2, %3;" : "=l"(d) : "l"(a), "l"(b), "l"(c));
    return d;
}
static __device__ __forceinline__ void mbar_wait(uint32_t mbar, uint32_t ph) {
    asm volatile(
        "{\n\t.reg .pred P;\n"
        "WL_%=:\n\t"
        "mbarrier.try_wait.parity.acquire.cta.shared::cta.b64 P, [%0], %1, 0x989680;\n\t"
        "@P bra WD_%=;\n\t"
        "bra WL_%=;\n"
        "WD_%=:\n\t}"
        :: "r"(mbar), "r"(ph) : "memory");
}
static __device__ __forceinline__ void mma_ts(uint32_t d, uint32_t a, ull b, uint32_t en) {
    asm volatile(
        "{\n\t.reg .pred p;\n\t"
        "setp.ne.u32 p, %5, 0;\n\t"
        "tcgen05.mma.cta_group::1.kind::f16 [%0], [%1], %2, %3, {%4,%4,%4,%4}, p;\n\t}"
        :: "r"(d), "r"(a), "l"(b), "r"(IDESC), "r"(0u), "r"(en) : "memory");
}
static __device__ __forceinline__ void bulk_copy(uint32_t dst, const void* src,
                                                 uint32_t bytes, uint32_t mbar) {
    asm volatile(
        "cp.async.bulk.shared::cluster.global.mbarrier::complete_tx::bytes [%0], [%1], %2, [%3];"
        :: "r"(dst), "l"(src), "r"(bytes), "r"(mbar) : "memory");
}
static __device__ __forceinline__ void expect_tx(uint32_t mbar, uint32_t bytes) {
    asm volatile("mbarrier.arrive.expect_tx.shared.b64 _, [%0], %1;"
                 :: "r"(mbar), "r"(bytes) : "memory");
}

#define STTM16(addr, r) asm volatile( \
    "tcgen05.st.sync.aligned.32x32b.x16.b32 [%0], " \
    "{%1,%2,%3,%4,%5,%6,%7,%8,%9,%10,%11,%12,%13,%14,%15,%16};" \
    :: "r"(addr), \
       "r"((r)[0]),"r"((r)[1]),"r"((r)[2]),"r"((r)[3]), \
       "r"((r)[4]),"r"((r)[5]),"r"((r)[6]),"r"((r)[7]), \
       "r"((r)[8]),"r"((r)[9]),"r"((r)[10]),"r"((r)[11]), \
       "r"((r)[12]),"r"((r)[13]),"r"((r)[14]),"r"((r)[15]) : "memory")

#define LDTM32(r, addr) asm volatile( \
    "tcgen05.ld.sync.aligned.32x32b.x32.b32 " \
    "{%0,%1,%2,%3,%4,%5,%6,%7,%8,%9,%10,%11,%12,%13,%14,%15," \
    "%16,%17,%18,%19,%20,%21,%22,%23,%24,%25,%26,%27,%28,%29,%30,%31}, [%32];" \
    : "=r"(r[0]),"=r"(r[1]),"=r"(r[2]),"=r"(r[3]),"=r"(r[4]),"=r"(r[5]),"=r"(r[6]),"=r"(r[7]), \
      "=r"(r[8]),"=r"(r[9]),"=r"(r[10]),"=r"(r[11]),"=r"(r[12]),"=r"(r[13]),"=r"(r[14]),"=r"(r[15]), \
      "=r"(r[16]),"=r"(r[17]),"=r"(r[18]),"=r"(r[19]),"=r"(r[20]),"=r"(r[21]),"=r"(r[22]),"=r"(r[23]), \
      "=r"(r[24]),"=r"(r[25]),"=r"(r[26]),"=r"(r[27]),"=r"(r[28]),"=r"(r[29]),"=r"(r[30]),"=r"(r[31]) \
    : "r"(addr))

// build A (hi/lo bf16) for one chunk directly into TMEM
static __device__ __forceinline__ void produce_a(
    uint32_t tmem_base, const char* w1buf, const ull* qq, int ab, int w)
{
    const ulonglong2* w1v = (const ulonglong2*)w1buf;
    const int kbase = (w >> 2) * 16;
    uint32_t hi[16], lo[16];
#pragma unroll
    for (int i = 0; i < 16; ++i) {
        const int kp = kbase + i;
        ull acc = 0ULL;
#pragma unroll
        for (int j = 0; j < 5; ++j) {
            ulonglong2 ww = w1v[kp * 5 + j];
            acc = fma2(qq[2 * j],     ww.x, acc);
            acc = fma2(qq[2 * j + 1], ww.y, acc);
        }
        float s0 = fmaxf(__uint_as_float((uint32_t)acc), 0.0f);
        float s1 = fmaxf(__uint_as_float((uint32_t)(acc >> 32)), 0.0f);
        cvt_split(s0, s1, hi[i], lo[i]);
    }
    const uint32_t woff = (uint32_t)(w & 3) << 21;        // subpartition
    const uint32_t aH = tmem_base + 256 + ab * 64 + kbase + woff;
    STTM16(aH, hi);
    STTM16(aH + 32, lo);
    asm volatile("tcgen05.wait::st.sync.aligned;" ::: "memory");
}
#endif  // TC_OK

__global__ __launch_bounds__(THREADS, 1)
void ffq_tc_kernel(const float* __restrict__ x,
                   const float* __restrict__ qp,
                   const float* __restrict__ W1,
                   float* __restrict__ out)
{
#if TC_OK
    extern __shared__ char smem[];
    const uint32_t sbase = smem_u32(smem);
    const int tid = threadIdx.x;
    const int w = tid >> 5, lane = tid & 31;
    const int nb = blockIdx.x;
    const int bm = blockIdx.y * BM;
    const int bn = nb * BN;

    if (tid < 32) {
        asm volatile("tcgen05.alloc.cta_group::1.sync.aligned.shared::cta.b32 [%0], %1;"
                     :: "r"(sbase + OFF_TMEM), "r"(512) : "memory");
        asm volatile("tcgen05.relinquish_alloc_permit.cta_group::1.sync.aligned;");
    }
    if (tid == 0) {
        asm volatile("mbarrier.init.shared.b64 [%0], %1;" :: "r"(sbase + OFF_MMA),     "r"(1u) : "memory");
        asm volatile("mbarrier.init.shared.b64 [%0], %1;" :: "r"(sbase + OFF_MMA + 8), "r"(1u) : "memory");
        asm volatile("mbarrier.init.shared.b64 [%0], %1;" :: "r"(sbase + OFF_BF),      "r"(1u) : "memory");
        asm volatile("mbarrier.init.shared.b64 [%0], %1;" :: "r"(sbase + OFF_BF + 8),  "r"(1u) : "memory");
        asm volatile("mbarrier.init.shared.b64 [%0], %1;" :: "r"(sbase + OFF_BF + 16), "r"(1u) : "memory");
    }
    __syncthreads();

    uint32_t tmem_base;
    asm volatile("ld.shared.b32 %0, [%1];" : "=r"(tmem_base) : "r"(sbase + OFF_TMEM));

    // ---- analytic quantum features for this thread's M row ----
    ull qq[NQ];
    {
        const int m = bm + 32 * (w & 3) + lane;
        float c[NQ];
#pragma unroll
        for (int j = 0; j < NQ; j++) c[j] = cosf(x[m * NQ + j] + qp[j]);
        float suf = 1.0f;
#pragma unroll
        for (int j = 1; j < NQ; j++) suf *= c[j];
        float qv[NQ];
        qv[0] = suf;
        float pre = c[0];
#pragma unroll
        for (int j = 1; j < NQ; j++) { pre *= c[j]; qv[j] = pre; }
#pragma unroll
        for (int j = 0; j < NQ; j++) {
            uint32_t b = __float_as_uint(qv[j]);
            qq[j] = ((ull)b << 32) | (ull)b;
        }
    }

    const unsigned char* gsrc = g_w2conv + (size_t)nb * NCHUNK * B_SLOT;

    // prologue: B copies for chunks 0,1 + W1 chunk 0 stage + A chunk 0
    if (w == 0 && elect_one()) {
#pragma unroll
        for (int s = 0; s < 2; ++s) {
            expect_tx(sbase + OFF_BF + s * 8, B_SLOT);
            bulk_copy(sbase + OFF_B + s * B_SLOT, gsrc + (size_t)s * B_SLOT,
                      B_SLOT, sbase + OFF_BF + s * 8);
        }
    }
    for (int i = tid; i < KC * NQ; i += THREADS) {
        int k = i / NQ, j = i - k * NQ;
        *(float*)(smem + OFF_W1 + (k >> 1) * 80 + j * 8 + (k & 1) * 4) = W1[i];
    }
    __syncthreads();
    produce_a(tmem_base, smem + OFF_W1, qq, 0, w);
    asm volatile("tcgen05.fence::before_thread_sync;" ::: "memory");
    __syncthreads();

    int phB[3] = {0, 0, 0};
    int phM[2] = {0, 0};

    for (int c = 0; c < NCHUNK; ++c) {
        const int bs = c % 3;
        const int ab = c & 1;

        if (w == 0) mbar_wait(sbase + OFF_BF + bs * 8, phB[bs]);
        phB[bs] ^= 1;

        if (w == 0 && elect_one()) {
            asm volatile("tcgen05.fence::after_thread_sync;" ::: "memory");
            const ull bH = make_desc(sbase + OFF_B + bs * B_SLOT);
            const ull bL = bH + (32768 >> 4);
            const uint32_t aH = tmem_base + 256 + ab * 64;
            const uint32_t aL = aH + 32;
#pragma unroll
            for (int ks = 0; ks < 4; ++ks)
                mma_ts(tmem_base, aH + ks * 8, bH + ks * 2, (c > 0) || (ks > 0));
#pragma unroll
            for (int ks = 0; ks < 4; ++ks) mma_ts(tmem_base, aL + ks * 8, bH + ks * 2, 1u);
#pragma unroll
            for (int ks = 0; ks < 4; ++ks) mma_ts(tmem_base, aH + ks * 8, bL + ks * 2, 1u);
            asm volatile("tcgen05.commit.cta_group::1.mbarrier::arrive::one.shared::cluster.b64 [%0];"
                         :: "r"(sbase + OFF_MMA + ab * 8) : "memory");
        }

        if (c > 0) {   // MMA c-1 done -> frees A buf (c+1)&1 and B slot (c+2)%3
            mbar_wait(sbase + OFF_MMA + (1 - ab) * 8, phM[1 - ab]);
            phM[1 - ab] ^= 1;
        }

        if (c + 2 < NCHUNK && w == 0 && elect_one()) {
            const int s2 = (c + 2) % 3;
            expect_tx(sbase + OFF_BF + s2 * 8, B_SLOT);
            bulk_copy(sbase + OFF_B + s2 * B_SLOT, gsrc + (size_t)(c + 2) * B_SLOT,
                      B_SLOT, sbase + OFF_BF + s2 * 8);
        }

        if (c + 1 < NCHUNK) {
            const int wb = (c + 1) & 1;
            const float* wsrc = W1 + (size_t)(c + 1) * KC * NQ;
            char* wdst = smem + OFF_W1 + wb * 2560;
            for (int i = tid; i < KC * NQ; i += THREADS) {
                int k = i / NQ, j = i - k * NQ;
                *(float*)(wdst + (k >> 1) * 80 + j * 8 + (k & 1) * 4) = wsrc[i];
            }
            __syncthreads();
            produce_a(tmem_base, wdst, qq, wb, w);
            asm volatile("tcgen05.fence::before_thread_sync;" ::: "memory");
        }
        __syncthreads();
    }

    // final MMA (chunk 63, parity 1)
    mbar_wait(sbase + OFF_MMA + 8, phM[1]);
    asm volatile("tcgen05.fence::after_thread_sync;" ::: "memory");

    // ---- epilogue: D (TMEM cols 0..255) -> GMEM ----
    {
        const int c0 = (w >> 2) * 128;
        const int m = bm + 32 * (w & 3) + lane;
        float* orow = out + (size_t)m * NDIM + bn + c0;
#pragma unroll
        for (int q = 0; q < 4; ++q) {
            uint32_t r[32];
            LDTM32(r, tmem_base + c0 + q * 32);
            asm volatile("tcgen05.wait::ld.sync.aligned;" ::: "memory");
#pragma unroll
            for (int i = 0; i < 8; ++i) {
                *(float4*)(orow + q * 32 + 4 * i) =
                    make_float4(__uint_as_float(r[4 * i]), __uint_as_float(r[4 * i + 1]),
                                __uint_as_float(r[4 * i + 2]), __uint_as_float(r[4 * i + 3]));
            }
        }
    }

    __syncthreads();
    if (tid < 32) {
        asm volatile("tcgen05.dealloc.cta_group::1.sync.aligned.b32 %0, %1;"
                     :: "r"(tmem_base), "r"(512));
    }
#endif  // TC_OK
}

// ============================================================================
// Kernel B: known-good FFMA fallback (round 2) — active only WITHOUT SM103_ALL
// ============================================================================
#define FBM 128
#define FBN 128
#define FBK 16

__global__ __launch_bounds__(256)
void ffq_fused_kernel(const float* __restrict__ x,
                      const float* __restrict__ qp,
                      const float* __restrict__ W1,
                      const float* __restrict__ W2,
                      float* __restrict__ out)
{
#if !TC_OK
    __shared__ float qs[FBM][NQ];
    __shared__ float As[FBK][FBM];
    __shared__ float Bs[FBK][FBN];

    const int tid = threadIdx.x;
    const int bm  = blockIdx.y * FBM;
    const int bn  = blockIdx.x * FBN;

    if (tid < FBM) {
        const int r = bm + tid;
        float c[NQ];
#pragma unroll
        for (int j = 0; j < NQ; j++) c[j] = cosf(x[r * NQ + j] + qp[j]);
        float suf = 1.0f;
#pragma unroll
        for (int j = 1; j < NQ; j++) suf *= c[j];
        qs[tid][0] = suf;
        float pre = c[0];
#pragma unroll
        for (int j = 1; j < NQ; j++) { pre *= c[j]; qs[tid][j] = pre; }
    }
    __syncthreads();

    const int ty = tid >> 4, tx = tid & 15;
    const int a_m = tid >> 1, a_kh = (tid & 1) * 8;

    float acc[8][8];
#pragma unroll
    for (int i = 0; i < 8; i++)
#pragma unroll
        for (int j = 0; j < 8; j++) acc[i][j] = 0.0f;

    float qr[NQ];
#pragma unroll
    for (int j = 0; j < NQ; j++) qr[j] = qs[a_m][j];

    for (int kk = 0; kk < KDIM; kk += FBK) {
#pragma unroll
        for (int ki = 0; ki < 8; ki++) {
            const int k = a_kh + ki;
            const float* ww = &W1[(kk + k) * NQ];
            float s = 0.0f;
#pragma unroll
            for (int j = 0; j < NQ; j++) s += qr[j] * ww[j];
            As[k][a_m] = fmaxf(s, 0.0f);
        }
#pragma unroll
        for (int v = 0; v < 2; v++) {
            const int idx = tid + v * 256;
            const int nrow = idx >> 2, kc = (idx & 3) * 4;
            const float4 t = *(const float4*)&W2[(size_t)(bn + nrow) * KDIM + kk + kc];
            Bs[kc + 0][nrow] = t.x; Bs[kc + 1][nrow] = t.y;
            Bs[kc + 2][nrow] = t.z; Bs[kc + 3][nrow] = t.w;
        }
        __syncthreads();
#pragma unroll
        for (int k = 0; k < FBK; k++) {
            float a[8], b[8];
            const float4 a0 = *(const float4*)&As[k][ty * 8];
            const float4 a1 = *(const float4*)&As[k][ty * 8 + 4];
            const float4 b0 = *(const float4*)&Bs[k][tx * 8];
            const float4 b1 = *(const float4*)&Bs[k][tx * 8 + 4];
            a[0]=a0.x;a[1]=a0.y;a[2]=a0.z;a[3]=a0.w;a[4]=a1.x;a[5]=a1.y;a[6]=a1.z;a[7]=a1.w;
            b[0]=b0.x;b[1]=b0.y;b[2]=b0.z;b[3]=b0.w;b[4]=b1.x;b[5]=b1.y;b[6]=b1.z;b[7]=b1.w;
#pragma unroll
            for (int i = 0; i < 8; i++)
#pragma unroll
                for (int j = 0; j < 8; j++) acc[i][j] += a[i] * b[j];
        }
        __syncthreads();
    }
#pragma unroll
    for (int i = 0; i < 8; i++) {
        const int m = bm + ty * 8 + i;
        float* o = &out[(size_t)m * NDIM + bn + tx * 8];
        *(float4*)&o[0] = make_float4(acc[i][0], acc[i][1], acc[i][2], acc[i][3]);
        *(float4*)&o[4] = make_float4(acc[i][4], acc[i][5], acc[i][6], acc[i][7]);
    }
#endif  // !TC_OK
}

extern "C" void kernel_launch(void* const* d_in, const int* in_sizes, int n_in,
                              void* d_out, int out_size)
{
    const float* x  = (const float*)d_in[0];
    const float* qp = (const float*)d_in[1];
    const float* W1 = (const float*)d_in[2];
    const float* W2 = (const float*)d_in[3];
    float* out = (float*)d_out;

    const int M = in_sizes[0] / NQ;   // 16384

    // probe which SASS variant got loaded: empty bodies compile to <=~24 regs
    cudaFuncAttributes fa; fa.numRegs = 0;
    cudaError_t qerr = cudaFuncGetAttributes(&fa, ffq_tc_kernel);
    const bool tc = (qerr == cudaSuccess) && (fa.numRegs > 32);

    if (tc || qerr != cudaSuccess) {
        convert_w2_kernel<<<(NDIM * KDIM / 8) / 256, 256>>>(W2);
        cudaFuncSetAttribute(ffq_tc_kernel, cudaFuncAttributeMaxDynamicSharedMemorySize, SMEM_BYTES);
        dim3 grid(NBLK, M / BM);      // (4, 128)
        ffq_tc_kernel<<<grid, THREADS, SMEM_BYTES>>>(x, qp, W1, out);
    }
    if (!tc) {
        dim3 gridB(NDIM / FBN, M / FBM);
        ffq_fused_kernel<<<gridB, 256>>>(x, qp, W1, W2, out);
    }
}

// round 6
// speedup vs baseline: 9.4645x; 1.5405x over previous
#include <cuda_runtime.h>
#include <cuda_bf16.h>
#include <math.h>
#include <stdint.h>

typedef unsigned long long ull;

#define NQ      10
#define KDIM    4096
#define NDIM    1024
#define BM      128
#define BN      256
#define KC      64
#define NCHUNK  64
#define THREADS 544
#define NBLK    (NDIM / BN)          // 4

#if defined(__CUDA_ARCH__) && defined(__CUDA_ARCH_HAS_FEATURE__)
#  if __CUDA_ARCH_HAS_FEATURE__(SM103_ALL) || __CUDA_ARCH_HAS_FEATURE__(SM100_ALL)
#    define TC_OK 1
#  endif
#endif
#ifndef TC_OK
#  define TC_OK 0
#endif

// SMEM layout
#define OFF_TMEM 0
#define OFF_MD   16                  // 4 x 8B mma-done
#define OFF_BF   48                  // 3 x 8B b-full
#define OFF_AR   80                  // 4 x 8B a-ready (count 16)
#define OFF_W1   128                 // 2 x 2560B W1 staging
#define OFF_B    8192                // 3 slots x 64KB (hi 32KB | lo 32KB)
#define B_SLOT   65536
#define SMEM_BYTES (OFF_B + 3 * B_SLOT)   // 204800

// idesc kind::f16: dtype=F32, a/b=BF16, M=128, N=256
#define IDESC 0x08400490u
#define SW128(o) ((o) ^ (((o) >> 3) & 0x70))

// converted W2: [nb][chunk][hi 32KB | lo 32KB] pre-swizzled tile images (16MB)
__device__ __align__(1024) unsigned char g_w2conv[(size_t)NBLK * NCHUNK * B_SLOT];

static __device__ __forceinline__ uint32_t pack_bf16(float lo, float hi) {
    uint32_t r;
    asm("cvt.rn.bf16x2.f32 %0, %1, %2;" : "=r"(r) : "f"(hi), "f"(lo));
    return r;
}
static __device__ __forceinline__ void cvt_split(float x0, float x1, uint32_t& h, uint32_t& l) {
    h = pack_bf16(x0, x1);
    float h0 = __uint_as_float(h << 16);
    float h1 = __uint_as_float(h & 0xFFFF0000u);
    l = pack_bf16(x0 - h0, x1 - h1);
}

// ============================================================================
// Kernel 0: W2 fp32 -> bf16 hi/lo, SW128-swizzled tile images
// ============================================================================
__global__ __launch_bounds__(256)
void convert_w2_kernel(const float* __restrict__ W2)
{
    const int t   = blockIdx.x * 256 + threadIdx.x;
    const int row = t >> 9;
    const int k0  = (t & 511) << 3;
    const int nb  = row >> 8, n = row & 255;
    const int c   = k0 >> 6,  k = k0 & 63;

    const float4* p = (const float4*)(W2 + (size_t)row * KDIM + k0);
    const float4 u = p[0], v = p[1];
    uint32_t h0, h1, h2, h3, l0, l1, l2, l3;
    cvt_split(u.x, u.y, h0, l0);
    cvt_split(u.z, u.w, h1, l1);
    cvt_split(v.x, v.y, h2, l2);
    cvt_split(v.z, v.w, h3, l3);

    unsigned char* base = g_w2conv + ((size_t)(nb * NCHUNK + c)) * B_SLOT;
    const uint32_t off = SW128((uint32_t)(n * 128 + k * 2));
    *(uint4*)(base + off)         = make_uint4(h0, h1, h2, h3);
    *(uint4*)(base + 32768 + off) = make_uint4(l0, l1, l2, l3);
}

// ============================================================================
// Kernel A: warp-specialized TS-mode tcgen05 GEMM
// ============================================================================
#if TC_OK
static __device__ __forceinline__ uint32_t smem_u32(const void* p) {
    uint32_t a;
    asm("{ .reg .u64 t; cvta.to.shared.u64 t, %1; cvt.u32.u64 %0, t; }" : "=r"(a) : "l"(p));
    return a;
}
static __device__ __forceinline__ bool elect_one() {
    uint32_t p;
    asm volatile("{ .reg .pred P; elect.sync _|P, 0xFFFFFFFF; selp.b32 %0, 1, 0, P; }" : "=r"(p));
    return p != 0;
}
static __device__ __forceinline__ ull make_desc(uint32_t addr) {  // SW128 K-major
    return (2ULL << 61) | (1ULL << 46) | (64ULL << 32) | (1ULL << 16) |
           (ull)((addr >> 4) & 0x3FFF);
}
static __device__ __forceinline__ ull fma2(ull a, ull b, ull c) {
    ull d;
    asm("fma.rn.f32x2 %0, %1, %2, %3;" : "=l"(d) : "l"(a), "l"(b), "l"(c));
    return d;
}
static __device__ __forceinline__ void mbar_wait(uint32_t mbar, uint32_t ph) {
    asm volatile(
        "{\n\t.reg .pred P;\n"
        "WL_%=:\n\t"
        "mbarrier.try_wait.parity.acquire.cta.shared::cta.b64 P, [%0], %1, 0x989680;\n\t"
        "@P bra WD_%=;\n\t"
        "bra WL_%=;\n"
        "WD_%=:\n\t}"
        :: "r"(mbar), "r"(ph) : "memory");
}
static __device__ __forceinline__ void mbar_arrive(uint32_t mbar) {
    asm volatile("mbarrier.arrive.shared.b64 _, [%0];" :: "r"(mbar) : "memory");
}
static __device__ __forceinline__ void mma_ts(uint32_t d, uint32_t a, ull b, uint32_t en) {
    asm volatile(
        "{\n\t.reg .pred p;\n\t"
        "setp.ne.u32 p, %5, 0;\n\t"
        "tcgen05.mma.cta_group::1.kind::f16 [%0], [%1], %2, %3, {%4,%4,%4,%4}, p;\n\t}"
        :: "r"(d), "r"(a), "l"(b), "r"(IDESC), "r"(0u), "r"(en) : "memory");
}
static __device__ __forceinline__ void bulk_copy(uint32_t dst, const void* src,
                                                 uint32_t bytes, uint32_t mbar) {
    asm volatile(
        "cp.async.bulk.shared::cluster.global.mbarrier::complete_tx::bytes [%0], [%1], %2, [%3];"
        :: "r"(dst), "l"(src), "r"(bytes), "r"(mbar) : "memory");
}
static __device__ __forceinline__ void expect_tx(uint32_t mbar, uint32_t bytes) {
    asm volatile("mbarrier.arrive.expect_tx.shared.b64 _, [%0], %1;"
                 :: "r"(mbar), "r"(bytes) : "memory");
}

#define STTM8(addr, r) asm volatile( \
    "tcgen05.st.sync.aligned.32x32b.x8.b32 [%0], {%1,%2,%3,%4,%5,%6,%7,%8};" \
    :: "r"(addr), "r"((r)[0]),"r"((r)[1]),"r"((r)[2]),"r"((r)[3]), \
       "r"((r)[4]),"r"((r)[5]),"r"((r)[6]),"r"((r)[7]) : "memory")

#define LDTM32(r, addr) asm volatile( \
    "tcgen05.ld.sync.aligned.32x32b.x32.b32 " \
    "{%0,%1,%2,%3,%4,%5,%6,%7,%8,%9,%10,%11,%12,%13,%14,%15," \
    "%16,%17,%18,%19,%20,%21,%22,%23,%24,%25,%26,%27,%28,%29,%30,%31}, [%32];" \
    : "=r"(r[0]),"=r"(r[1]),"=r"(r[2]),"=r"(r[3]),"=r"(r[4]),"=r"(r[5]),"=r"(r[6]),"=r"(r[7]), \
      "=r"(r[8]),"=r"(r[9]),"=r"(r[10]),"=r"(r[11]),"=r"(r[12]),"=r"(r[13]),"=r"(r[14]),"=r"(r[15]), \
      "=r"(r[16]),"=r"(r[17]),"=r"(r[18]),"=r"(r[19]),"=r"(r[20]),"=r"(r[21]),"=r"(r[22]),"=r"(r[23]), \
      "=r"(r[24]),"=r"(r[25]),"=r"(r[26]),"=r"(r[27]),"=r"(r[28]),"=r"(r[29]),"=r"(r[30]),"=r"(r[31]) \
    : "r"(addr))

// produce 8 kpairs of A (hi/lo bf16) into TMEM buffer
static __device__ __forceinline__ void produce8(
    uint32_t tmem_base, const char* w1buf, const ull* qq, int buf, int sp, int kg)
{
    const ulonglong2* w1v = (const ulonglong2*)w1buf;
    uint32_t hi[8], lo[8];
#pragma unroll
    for (int i = 0; i < 8; ++i) {
        const int kp = kg * 8 + i;
        ull acc = 0ULL;
#pragma unroll
        for (int j = 0; j < 5; ++j) {
            ulonglong2 ww = w1v[kp * 5 + j];
            acc = fma2(qq[2 * j],     ww.x, acc);
            acc = fma2(qq[2 * j + 1], ww.y, acc);
        }
        float s0 = fmaxf(__uint_as_float((uint32_t)acc), 0.0f);
        float s1 = fmaxf(__uint_as_float((uint32_t)(acc >> 32)), 0.0f);
        cvt_split(s0, s1, hi[i], lo[i]);
    }
    const uint32_t a = tmem_base + 256 + buf * 64 + kg * 8 + ((uint32_t)sp << 21);
    STTM8(a, hi);
    STTM8(a + 32, lo);
    asm volatile("tcgen05.wait::st.sync.aligned;" ::: "memory");
}
#endif  // TC_OK

__global__ __launch_bounds__(THREADS, 1)
void ffq_tc_kernel(const float* __restrict__ x,
                   const float* __restrict__ qp,
                   const float* __restrict__ W1,
                   float* __restrict__ out)
{
#if TC_OK
    extern __shared__ char smem[];
    const uint32_t sbase = smem_u32(smem);
    const int tid = threadIdx.x;
    const int w = tid >> 5, lane = tid & 31;
    const int nb = blockIdx.x;
    const int bm = blockIdx.y * BM;
    const int bn = nb * BN;

    const uint32_t MD = sbase + OFF_MD;
    const uint32_t BF = sbase + OFF_BF;
    const uint32_t AR = sbase + OFF_AR;
    const unsigned char* gsrc = g_w2conv + (size_t)nb * NCHUNK * B_SLOT;

    if (w == 0) {
        asm volatile("tcgen05.alloc.cta_group::1.sync.aligned.shared::cta.b32 [%0], %1;"
                     :: "r"(sbase + OFF_TMEM), "r"(512) : "memory");
        asm volatile("tcgen05.relinquish_alloc_permit.cta_group::1.sync.aligned;");
        if (elect_one()) {
#pragma unroll
            for (int i = 0; i < 4; ++i) {
                asm volatile("mbarrier.init.shared.b64 [%0], %1;" :: "r"(MD + 8*i), "r"(1u)  : "memory");
                asm volatile("mbarrier.init.shared.b64 [%0], %1;" :: "r"(AR + 8*i), "r"(16u) : "memory");
            }
#pragma unroll
            for (int i = 0; i < 3; ++i)
                asm volatile("mbarrier.init.shared.b64 [%0], %1;" :: "r"(BF + 8*i), "r"(1u) : "memory");
            // prologue B copies: chunks 0,1,2
#pragma unroll
            for (int s = 0; s < 3; ++s) {
                expect_tx(BF + 8*s, B_SLOT);
                bulk_copy(sbase + OFF_B + s * B_SLOT, gsrc + (size_t)s * B_SLOT,
                          B_SLOT, BF + 8*s);
            }
        }
    }
    __syncthreads();

    uint32_t tmem_base;
    asm volatile("ld.shared.b32 %0, [%1];" : "=r"(tmem_base) : "r"(sbase + OFF_TMEM));

    if (w == 0) {
        // ===================== scheduler warp =====================
        if (elect_one()) {
            int phar[4] = {0,0,0,0}, phmd[4] = {0,0,0,0}, phbf[3] = {0,0,0};
            for (int c = 0; c < NCHUNK; ++c) {
                const int ai = c & 3, bs = c % 3;
                mbar_wait(AR + 8*ai, phar[ai] & 1); phar[ai]++;
                mbar_wait(BF + 8*bs, phbf[bs] & 1); phbf[bs]++;
                asm volatile("tcgen05.fence::after_thread_sync;" ::: "memory");
                const ull bH = make_desc(sbase + OFF_B + bs * B_SLOT);
                const ull bL = bH + (32768 >> 4);
                const uint32_t aH = tmem_base + 256 + ai * 64;
                const uint32_t aL = aH + 32;
#pragma unroll
                for (int ks = 0; ks < 4; ++ks)
                    mma_ts(tmem_base, aH + ks * 8, bH + ks * 2, (c > 0) || (ks > 0));
#pragma unroll
                for (int ks = 0; ks < 4; ++ks) mma_ts(tmem_base, aL + ks * 8, bH + ks * 2, 1u);
#pragma unroll
                for (int ks = 0; ks < 4; ++ks) mma_ts(tmem_base, aH + ks * 8, bL + ks * 2, 1u);
                asm volatile("tcgen05.commit.cta_group::1.mbarrier::arrive::one.shared::cluster.b64 [%0];"
                             :: "r"(MD + 8*ai) : "memory");
                if (c >= 1) {
                    const int pi = (c - 1) & 3;
                    mbar_wait(MD + 8*pi, phmd[pi] & 1); phmd[pi]++;
                    if (c + 2 < NCHUNK) {
                        const int s2 = (c + 2) % 3;
                        expect_tx(BF + 8*s2, B_SLOT);
                        bulk_copy(sbase + OFF_B + s2 * B_SLOT,
                                  gsrc + (size_t)(c + 2) * B_SLOT, B_SLOT, BF + 8*s2);
                    }
                }
            }
        }
    } else {
        // ===================== producer warps (1..16) =====================
        const int sp = w & 3;             // TMEM subpartition (physical warp%4)
        const int kg = (w - 1) >> 2;      // k-group 0..3
        const int pt = tid - 32;          // 0..511

        // analytic quantum features for row m
        ull qq[NQ];
        {
            const int m = bm + sp * 32 + lane;
            float c[NQ];
#pragma unroll
            for (int j = 0; j < NQ; j++) c[j] = cosf(x[m * NQ + j] + qp[j]);
            float suf = 1.0f;
#pragma unroll
            for (int j = 1; j < NQ; j++) suf *= c[j];
            float qv[NQ];
            qv[0] = suf;
            float pre = c[0];
#pragma unroll
            for (int j = 1; j < NQ; j++) { pre *= c[j]; qv[j] = pre; }
#pragma unroll
            for (int j = 0; j < NQ; j++) {
                uint32_t b = __float_as_uint(qv[j]);
                qq[j] = ((ull)b << 32) | (ull)b;
            }
        }

        // W1 staging: each thread owns elements pt and (512+pt if pt<128)
        uint32_t off1, off2;
        {
            int k1 = pt / NQ, j1 = pt - k1 * NQ;
            off1 = (k1 >> 1) * 80 + j1 * 8 + (k1 & 1) * 4;
            int i2 = 512 + pt, k2 = i2 / NQ, j2 = i2 - k2 * NQ;
            off2 = (k2 >> 1) * 80 + j2 * 8 + (k2 & 1) * 4;
        }
        // stage W1(0), W1(1)
        {
            const float* ws = W1;
            float a1 = ws[pt], a2 = (pt < 128) ? ws[512 + pt] : 0.0f;
            *(float*)(smem + OFF_W1 + off1) = a1;
            if (pt < 128) *(float*)(smem + OFF_W1 + off2) = a2;
            ws = W1 + KC * NQ;
            a1 = ws[pt]; a2 = (pt < 128) ? ws[512 + pt] : 0.0f;
            *(float*)(smem + OFF_W1 + 2560 + off1) = a1;
            if (pt < 128) *(float*)(smem + OFF_W1 + 2560 + off2) = a2;
        }
        asm volatile("bar.sync 1, 512;" ::: "memory");

        // produce A(0) into buf 0
        produce8(tmem_base, smem + OFF_W1, qq, 0, sp, kg);
        asm volatile("tcgen05.fence::before_thread_sync;" ::: "memory");
        if (elect_one()) mbar_arrive(AR + 0);

        int phmd[4] = {0,0,0,0};

        for (int c = 0; c < NCHUNK - 1; ++c) {
            // early W1 LDG for chunk c+2
            float a1 = 0.0f, a2 = 0.0f;
            const bool haveW = (c + 2 < NCHUNK);
            if (haveW) {
                const float* ws = W1 + (size_t)(c + 2) * KC * NQ;
                a1 = __ldg(&ws[pt]);
                if (pt < 128) a2 = __ldg(&ws[512 + pt]);
            }
            if (c >= 3) {
                const int mi = (c - 3) & 3;
                mbar_wait(MD + 8*mi, phmd[mi] & 1); phmd[mi]++;
            }
            // produce A(c+1)
            produce8(tmem_base, smem + OFF_W1 + ((c + 1) & 1) * 2560, qq,
                     (c + 1) & 3, sp, kg);
            asm volatile("tcgen05.fence::before_thread_sync;" ::: "memory");
            if (elect_one()) mbar_arrive(AR + 8 * ((c + 1) & 3));
            if (haveW) {
                char* wd = smem + OFF_W1 + ((c + 2) & 1) * 2560;
                *(float*)(wd + off1) = a1;
                if (pt < 128) *(float*)(wd + off2) = a2;
            }
            asm volatile("bar.sync 1, 512;" ::: "memory");
        }

        // wait final MMA (chunk 63 -> MD[3])
        mbar_wait(MD + 8*3, phmd[3] & 1);
        asm volatile("tcgen05.fence::after_thread_sync;" ::: "memory");

        // epilogue: D cols kg*64 .. kg*64+63, rows sp*32+lane
        {
            const int m = bm + sp * 32 + lane;
            float* orow = out + (size_t)m * NDIM + bn + kg * 64;
#pragma unroll
            for (int q = 0; q < 2; ++q) {
                uint32_t r[32];
                LDTM32(r, tmem_base + kg * 64 + q * 32);
                asm volatile("tcgen05.wait::ld.sync.aligned;" ::: "memory");
#pragma unroll
                for (int i = 0; i < 8; ++i) {
                    *(float4*)(orow + q * 32 + 4 * i) =
                        make_float4(__uint_as_float(r[4*i]), __uint_as_float(r[4*i+1]),
                                    __uint_as_float(r[4*i+2]), __uint_as_float(r[4*i+3]));
                }
            }
        }
    }

    __syncthreads();
    if (w == 0) {
        asm volatile("tcgen05.dealloc.cta_group::1.sync.aligned.b32 %0, %1;"
                     :: "r"(tmem_base), "r"(512));
    }
#endif  // TC_OK
}

// ============================================================================
// Kernel B: known-good FFMA fallback — active only WITHOUT SM103_ALL
// ============================================================================
#define FBM 128
#define FBN 128
#define FBK 16

__global__ __launch_bounds__(256)
void ffq_fused_kernel(const float* __restrict__ x,
                      const float* __restrict__ qp,
                      const float* __restrict__ W1,
                      const float* __restrict__ W2,
                      float* __restrict__ out)
{
#if !TC_OK
    __shared__ float qs[FBM][NQ];
    __shared__ float As[FBK][FBM];
    __shared__ float Bs[FBK][FBN];

    const int tid = threadIdx.x;
    const int bm  = blockIdx.y * FBM;
    const int bn  = blockIdx.x * FBN;

    if (tid < FBM) {
        const int r = bm + tid;
        float c[NQ];
#pragma unroll
        for (int j = 0; j < NQ; j++) c[j] = cosf(x[r * NQ + j] + qp[j]);
        float suf = 1.0f;
#pragma unroll
        for (int j = 1; j < NQ; j++) suf *= c[j];
        qs[tid][0] = suf;
        float pre = c[0];
#pragma unroll
        for (int j = 1; j < NQ; j++) { pre *= c[j]; qs[tid][j] = pre; }
    }
    __syncthreads();

    const int ty = tid >> 4, tx = tid & 15;
    const int a_m = tid >> 1, a_kh = (tid & 1) * 8;

    float acc[8][8];
#pragma unroll
    for (int i = 0; i < 8; i++)
#pragma unroll
        for (int j = 0; j < 8; j++) acc[i][j] = 0.0f;

    float qr[NQ];
#pragma unroll
    for (int j = 0; j < NQ; j++) qr[j] = qs[a_m][j];

    for (int kk = 0; kk < KDIM; kk += FBK) {
#pragma unroll
        for (int ki = 0; ki < 8; ki++) {
            const int k = a_kh + ki;
            const float* ww = &W1[(kk + k) * NQ];
            float s = 0.0f;
#pragma unroll
            for (int j = 0; j < NQ; j++) s += qr[j] * ww[j];
            As[k][a_m] = fmaxf(s, 0.0f);
        }
#pragma unroll
        for (int v = 0; v < 2; v++) {
            const int idx = tid + v * 256;
            const int nrow = idx >> 2, kc = (idx & 3) * 4;
            const float4 t = *(const float4*)&W2[(size_t)(bn + nrow) * KDIM + kk + kc];
            Bs[kc + 0][nrow] = t.x; Bs[kc + 1][nrow] = t.y;
            Bs[kc + 2][nrow] = t.z; Bs[kc + 3][nrow] = t.w;
        }
        __syncthreads();
#pragma unroll
        for (int k = 0; k < FBK; k++) {
            float a[8], b[8];
            const float4 a0 = *(const float4*)&As[k][ty * 8];
            const float4 a1 = *(const float4*)&As[k][ty * 8 + 4];
            const float4 b0 = *(const float4*)&Bs[k][tx * 8];
            const float4 b1 = *(const float4*)&Bs[k][tx * 8 + 4];
            a[0]=a0.x;a[1]=a0.y;a[2]=a0.z;a[3]=a0.w;a[4]=a1.x;a[5]=a1.y;a[6]=a1.z;a[7]=a1.w;
            b[0]=b0.x;b[1]=b0.y;b[2]=b0.z;b[3]=b0.w;b[4]=b1.x;b[5]=b1.y;b[6]=b1.z;b[7]=b1.w;
#pragma unroll
            for (int i = 0; i < 8; i++)
#pragma unroll
                for (int j = 0; j < 8; j++) acc[i][j] += a[i] * b[j];
        }
        __syncthreads();
    }
#pragma unroll
    for (int i = 0; i < 8; i++) {
        const int m = bm + ty * 8 + i;
        float* o = &out[(size_t)m * NDIM + bn + tx * 8];
        *(float4*)&o[0] = make_float4(acc[i][0], acc[i][1], acc[i][2], acc[i][3]);
        *(float4*)&o[4] = make_float4(acc[i][4], acc[i][5], acc[i][6], acc[i][7]);
    }
#endif  // !TC_OK
}

extern "C" void kernel_launch(void* const* d_in, const int* in_sizes, int n_in,
                              void* d_out, int out_size)
{
    const float* x  = (const float*)d_in[0];
    const float* qp = (const float*)d_in[1];
    const float* W1 = (const float*)d_in[2];
    const float* W2 = (const float*)d_in[3];
    float* out = (float*)d_out;

    const int M = in_sizes[0] / NQ;   // 16384

    cudaFuncAttributes fa; fa.numRegs = 0;
    cudaError_t qerr = cudaFuncGetAttributes(&fa, ffq_tc_kernel);
    const bool tc = (qerr == cudaSuccess) && (fa.numRegs > 32);

    if (tc || qerr != cudaSuccess) {
        convert_w2_kernel<<<(NDIM * KDIM / 8) / 256, 256>>>(W2);
        cudaFuncSetAttribute(ffq_tc_kernel, cudaFuncAttributeMaxDynamicSharedMemorySize, SMEM_BYTES);
        dim3 grid(NBLK, M / BM);      // (4, 128)
        ffq_tc_kernel<<<grid, THREADS, SMEM_BYTES>>>(x, qp, W1, out);
    }
    if (!tc) {
        dim3 gridB(NDIM / FBN, M / FBM);
        ffq_fused_kernel<<<gridB, 256>>>(x, qp, W1, W2, out);
    }
}

// round 7
// speedup vs baseline: 10.0189x; 1.0586x over previous
#include <cuda_runtime.h>
#include <cuda_bf16.h>
#include <math.h>
#include <stdint.h>

typedef unsigned long long ull;

#define NQ      10
#define KDIM    4096
#define NDIM    1024
#define BM      128
#define BN      256
#define KC      64
#define NCHUNK  64
#define NITER   32                   // chunk pairs
#define THREADS 544
#define NBLK    (NDIM / BN)          // 4

#if defined(__CUDA_ARCH__) && defined(__CUDA_ARCH_HAS_FEATURE__)
#  if __CUDA_ARCH_HAS_FEATURE__(SM103_ALL) || __CUDA_ARCH_HAS_FEATURE__(SM100_ALL)
#    define TC_OK 1
#  endif
#endif
#ifndef TC_OK
#  define TC_OK 0
#endif

// SMEM layout
#define OFF_TMEM 0
#define OFF_MD   16                  // 2 x 8B mma-pair-done
#define OFF_BF   32                  // 3 x 8B b-full
#define OFF_AR   64                  // 2 x 8B a-pair-ready (count 16)
#define OFF_W1   128                 // 2 x 5120B W1 pair staging
#define OFF_B    16384               // 3 slots x 64KB (hi 32KB | lo 32KB)
#define B_SLOT   65536
#define SMEM_BYTES (OFF_B + 3 * B_SLOT)   // 212992

// idesc kind::f16: dtype=F32, a/b=BF16, M=128, N=256
#define IDESC 0x08400490u
#define SW128(o) ((o) ^ (((o) >> 3) & 0x70))

// converted W2: [nb][chunk][hi 32KB | lo 32KB] pre-swizzled tile images (16MB)
__device__ __align__(1024) unsigned char g_w2conv[(size_t)NBLK * NCHUNK * B_SLOT];

static __device__ __forceinline__ uint32_t pack_bf16(float lo, float hi) {
    uint32_t r;
    asm("cvt.rn.bf16x2.f32 %0, %1, %2;" : "=r"(r) : "f"(hi), "f"(lo));
    return r;
}
static __device__ __forceinline__ void cvt_split(float x0, float x1, uint32_t& h, uint32_t& l) {
    h = pack_bf16(x0, x1);
    float h0 = __uint_as_float(h << 16);
    float h1 = __uint_as_float(h & 0xFFFF0000u);
    l = pack_bf16(x0 - h0, x1 - h1);
}

// ============================================================================
// Kernel 0: W2 fp32 -> bf16 hi/lo, SW128-swizzled tile images
// ============================================================================
__global__ __launch_bounds__(256)
void convert_w2_kernel(const float* __restrict__ W2)
{
    const int t   = blockIdx.x * 256 + threadIdx.x;
    const int row = t >> 9;
    const int k0  = (t & 511) << 3;
    const int nb  = row >> 8, n = row & 255;
    const int c   = k0 >> 6,  k = k0 & 63;

    const float4* p = (const float4*)(W2 + (size_t)row * KDIM + k0);
    const float4 u = p[0], v = p[1];
    uint32_t h0, h1, h2, h3, l0, l1, l2, l3;
    cvt_split(u.x, u.y, h0, l0);
    cvt_split(u.z, u.w, h1, l1);
    cvt_split(v.x, v.y, h2, l2);
    cvt_split(v.z, v.w, h3, l3);

    unsigned char* base = g_w2conv + ((size_t)(nb * NCHUNK + c)) * B_SLOT;
    const uint32_t off = SW128((uint32_t)(n * 128 + k * 2));
    *(uint4*)(base + off)         = make_uint4(h0, h1, h2, h3);
    *(uint4*)(base + 32768 + off) = make_uint4(l0, l1, l2, l3);
}

// ============================================================================
// Kernel A: warp-specialized TS-mode tcgen05 GEMM, chunk-pair pipelined
// ============================================================================
#if TC_OK
static __device__ __forceinline__ uint32_t smem_u32(const void* p) {
    uint32_t a;
    asm("{ .reg .u64 t; cvta.to.shared.u64 t, %1; cvt.u32.u64 %0, t; }" : "=r"(a) : "l"(p));
    return a;
}
static __device__ __forceinline__ bool elect_one() {
    uint32_t p;
    asm volatile("{ .reg .pred P; elect.sync _|P, 0xFFFFFFFF; selp.b32 %0, 1, 0, P; }" : "=r"(p));
    return p != 0;
}
static __device__ __forceinline__ ull make_desc(uint32_t addr) {  // SW128 K-major
    return (2ULL << 61) | (1ULL << 46) | (64ULL << 32) | (1ULL << 16) |
           (ull)((addr >> 4) & 0x3FFF);
}
static __device__ __forceinline__ ull fma2(ull a, ull b, ull c) {
    ull d;
    asm("fma.rn.f32x2 %0, %1, %2, %3;" : "=l"(d) : "l"(a), "l"(b), "l"(c));
    return d;
}
static __device__ __forceinline__ void mbar_wait(uint32_t mbar, uint32_t ph) {
    asm volatile(
        "{\n\t.reg .pred P;\n"
        "WL_%=:\n\t"
        "mbarrier.try_wait.parity.acquire.cta.shared::cta.b64 P, [%0], %1, 0x989680;\n\t"
        "@P bra WD_%=;\n\t"
        "bra WL_%=;\n"
        "WD_%=:\n\t}"
        :: "r"(mbar), "r"(ph) : "memory");
}
static __device__ __forceinline__ void mbar_arrive(uint32_t mbar) {
    asm volatile("mbarrier.arrive.shared.b64 _, [%0];" :: "r"(mbar) : "memory");
}
static __device__ __forceinline__ void mma_ts(uint32_t d, uint32_t a, ull b, uint32_t en) {
    asm volatile(
        "{\n\t.reg .pred p;\n\t"
        "setp.ne.u32 p, %5, 0;\n\t"
        "tcgen05.mma.cta_group::1.kind::f16 [%0], [%1], %2, %3, {%4,%4,%4,%4}, p;\n\t}"
        :: "r"(d), "r"(a), "l"(b), "r"(IDESC), "r"(0u), "r"(en) : "memory");
}
static __device__ __forceinline__ void bulk_copy(uint32_t dst, const void* src,
                                                 uint32_t bytes, uint32_t mbar) {
    asm volatile(
        "cp.async.bulk.shared::cluster.global.mbarrier::complete_tx::bytes [%0], [%1], %2, [%3];"
        :: "r"(dst), "l"(src), "r"(bytes), "r"(mbar) : "memory");
}
static __device__ __forceinline__ void expect_tx(uint32_t mbar, uint32_t bytes) {
    asm volatile("mbarrier.arrive.expect_tx.shared.b64 _, [%0], %1;"
                 :: "r"(mbar), "r"(bytes) : "memory");
}

#define STTM8(addr, r) asm volatile( \
    "tcgen05.st.sync.aligned.32x32b.x8.b32 [%0], {%1,%2,%3,%4,%5,%6,%7,%8};" \
    :: "r"(addr), "r"((r)[0]),"r"((r)[1]),"r"((r)[2]),"r"((r)[3]), \
       "r"((r)[4]),"r"((r)[5]),"r"((r)[6]),"r"((r)[7]) : "memory")

#define LDTM32(r, addr) asm volatile( \
    "tcgen05.ld.sync.aligned.32x32b.x32.b32 " \
    "{%0,%1,%2,%3,%4,%5,%6,%7,%8,%9,%10,%11,%12,%13,%14,%15," \
    "%16,%17,%18,%19,%20,%21,%22,%23,%24,%25,%26,%27,%28,%29,%30,%31}, [%32];" \
    : "=r"(r[0]),"=r"(r[1]),"=r"(r[2]),"=r"(r[3]),"=r"(r[4]),"=r"(r[5]),"=r"(r[6]),"=r"(r[7]), \
      "=r"(r[8]),"=r"(r[9]),"=r"(r[10]),"=r"(r[11]),"=r"(r[12]),"=r"(r[13]),"=r"(r[14]),"=r"(r[15]), \
      "=r"(r[16]),"=r"(r[17]),"=r"(r[18]),"=r"(r[19]),"=r"(r[20]),"=r"(r[21]),"=r"(r[22]),"=r"(r[23]), \
      "=r"(r[24]),"=r"(r[25]),"=r"(r[26]),"=r"(r[27]),"=r"(r[28]),"=r"(r[29]),"=r"(r[30]),"=r"(r[31]) \
    : "r"(addr))

// produce 8 kpairs of A (hi/lo bf16) into one TMEM buffer
static __device__ __forceinline__ void produce8(
    uint32_t tmem_base, const char* w1buf, const ull* qq, int buf, int sp, int kg)
{
    const ulonglong2* w1v = (const ulonglong2*)w1buf;
    uint32_t hi[8], lo[8];
#pragma unroll
    for (int i = 0; i < 8; ++i) {
        const int kp = kg * 8 + i;
        ull acc = 0ULL;
#pragma unroll
        for (int j = 0; j < 5; ++j) {
            ulonglong2 ww = w1v[kp * 5 + j];
            acc = fma2(qq[2 * j],     ww.x, acc);
            acc = fma2(qq[2 * j + 1], ww.y, acc);
        }
        float s0 = fmaxf(__uint_as_float((uint32_t)acc), 0.0f);
        float s1 = fmaxf(__uint_as_float((uint32_t)(acc >> 32)), 0.0f);
        cvt_split(s0, s1, hi[i], lo[i]);
    }
    const uint32_t a = tmem_base + 256 + buf * 64 + kg * 8 + ((uint32_t)sp << 21);
    STTM8(a, hi);
    STTM8(a + 32, lo);
}

// W1 pair staging offset for linear element e in [0,1280)
static __device__ __forceinline__ uint32_t w1_off(int e) {
    const int ch = e / 640, rem = e - ch * 640;
    const int k = rem / NQ, j = rem - k * NQ;
    return (uint32_t)(ch * 2560 + (k >> 1) * 80 + j * 8 + (k & 1) * 4);
}
#endif  // TC_OK

__global__ __launch_bounds__(THREADS, 1)
void ffq_tc_kernel(const float* __restrict__ x,
                   const float* __restrict__ qp,
                   const float* __restrict__ W1,
                   float* __restrict__ out)
{
#if TC_OK
    extern __shared__ char smem[];
    const uint32_t sbase = smem_u32(smem);
    const int tid = threadIdx.x;
    const int w = tid >> 5, lane = tid & 31;
    const int nb = blockIdx.x;
    const int bm = blockIdx.y * BM;
    const int bn = nb * BN;

    const uint32_t MD = sbase + OFF_MD;
    const uint32_t BF = sbase + OFF_BF;
    const uint32_t AR = sbase + OFF_AR;
    const unsigned char* gsrc = g_w2conv + (size_t)nb * NCHUNK * B_SLOT;

    if (w == 0) {
        asm volatile("tcgen05.alloc.cta_group::1.sync.aligned.shared::cta.b32 [%0], %1;"
                     :: "r"(sbase + OFF_TMEM), "r"(512) : "memory");
        asm volatile("tcgen05.relinquish_alloc_permit.cta_group::1.sync.aligned;");
        if (elect_one()) {
#pragma unroll
            for (int i = 0; i < 2; ++i) {
                asm volatile("mbarrier.init.shared.b64 [%0], %1;" :: "r"(MD + 8*i), "r"(1u)  : "memory");
                asm volatile("mbarrier.init.shared.b64 [%0], %1;" :: "r"(AR + 8*i), "r"(16u) : "memory");
            }
#pragma unroll
            for (int i = 0; i < 3; ++i)
                asm volatile("mbarrier.init.shared.b64 [%0], %1;" :: "r"(BF + 8*i), "r"(1u) : "memory");
            // prologue B copies: chunks 0,1,2
#pragma unroll
            for (int s = 0; s < 3; ++s) {
                expect_tx(BF + 8*s, B_SLOT);
                bulk_copy(sbase + OFF_B + s * B_SLOT, gsrc + (size_t)s * B_SLOT,
                          B_SLOT, BF + 8*s);
            }
        }
    }
    __syncthreads();

    uint32_t tmem_base;
    asm volatile("ld.shared.b32 %0, [%1];" : "=r"(tmem_base) : "r"(sbase + OFF_TMEM));

    if (w == 0) {
        // ===================== scheduler warp =====================
        if (elect_one()) {
            int phar[2] = {0,0}, phbf[3] = {0,0,0};
            for (int i = 0; i < NITER; ++i) {
                const int pr = i & 1;
                const int s0 = (2*i) % 3;
                const int s1 = (2*i + 1) % 3;
                mbar_wait(AR + 8*pr, phar[pr] & 1); phar[pr]++;
                mbar_wait(BF + 8*s0, phbf[s0] & 1); phbf[s0]++;
                asm volatile("tcgen05.fence::after_thread_sync;" ::: "memory");
                {
                    const ull bH = make_desc(sbase + OFF_B + s0 * B_SLOT);
                    const ull bL = bH + (32768 >> 4);
                    const uint32_t aH = tmem_base + 256 + (2*pr) * 64;
                    const uint32_t aL = aH + 32;
#pragma unroll
                    for (int ks = 0; ks < 4; ++ks)
                        mma_ts(tmem_base, aH + ks*8, bH + ks*2, (i > 0) || (ks > 0));
#pragma unroll
                    for (int ks = 0; ks < 4; ++ks) mma_ts(tmem_base, aL + ks*8, bH + ks*2, 1u);
#pragma unroll
                    for (int ks = 0; ks < 4; ++ks) mma_ts(tmem_base, aH + ks*8, bL + ks*2, 1u);
                }
                mbar_wait(BF + 8*s1, phbf[s1] & 1); phbf[s1]++;
                {
                    const ull bH = make_desc(sbase + OFF_B + s1 * B_SLOT);
                    const ull bL = bH + (32768 >> 4);
                    const uint32_t aH = tmem_base + 256 + (2*pr + 1) * 64;
                    const uint32_t aL = aH + 32;
#pragma unroll
                    for (int ks = 0; ks < 4; ++ks) mma_ts(tmem_base, aH + ks*8, bH + ks*2, 1u);
#pragma unroll
                    for (int ks = 0; ks < 4; ++ks) mma_ts(tmem_base, aL + ks*8, bH + ks*2, 1u);
#pragma unroll
                    for (int ks = 0; ks < 4; ++ks) mma_ts(tmem_base, aH + ks*8, bL + ks*2, 1u);
                }
                asm volatile("tcgen05.commit.cta_group::1.mbarrier::arrive::one.shared::cluster.b64 [%0];"
                             :: "r"(MD + 8*pr) : "memory");
            }
        }
    } else {
        // ===================== producer warps (1..16) =====================
        const int sp = w & 3;             // TMEM subpartition
        const int kg = (w - 1) >> 2;      // k-group 0..3
        const int pt = tid - 32;          // 0..511

        ull qq[NQ];
        {
            const int m = bm + sp * 32 + lane;
            float c[NQ];
#pragma unroll
            for (int j = 0; j < NQ; j++) c[j] = cosf(x[m * NQ + j] + qp[j]);
            float suf = 1.0f;
#pragma unroll
            for (int j = 1; j < NQ; j++) suf *= c[j];
            float qv[NQ];
            qv[0] = suf;
            float pre = c[0];
#pragma unroll
            for (int j = 1; j < NQ; j++) { pre *= c[j]; qv[j] = pre; }
#pragma unroll
            for (int j = 0; j < NQ; j++) {
                uint32_t b = __float_as_uint(qv[j]);
                qq[j] = ((ull)b << 32) | (ull)b;
            }
        }

        const uint32_t off1 = w1_off(pt);
        const uint32_t off2 = w1_off(pt + 512);
        const uint32_t off3 = (pt < 256) ? w1_off(pt + 1024) : 0;

        // stage W1 pairs 0 and 1
#pragma unroll
        for (int p = 0; p < 2; ++p) {
            const float* ws = W1 + (size_t)p * 1280;
            char* wd = smem + OFF_W1 + p * 5120;
            *(float*)(wd + off1) = ws[pt];
            *(float*)(wd + off2) = ws[512 + pt];
            if (pt < 256) *(float*)(wd + off3) = ws[1024 + pt];
        }
        asm volatile("bar.sync 1, 512;" ::: "memory");

        // produce A pair 0 (bufs 0,1)
        produce8(tmem_base, smem + OFF_W1, qq, 0, sp, kg);
        produce8(tmem_base, smem + OFF_W1 + 2560, qq, 1, sp, kg);
        asm volatile("tcgen05.wait::st.sync.aligned;" ::: "memory");
        asm volatile("tcgen05.fence::before_thread_sync;" ::: "memory");
        if (elect_one()) mbar_arrive(AR + 0);

        int phmd[2] = {0,0};

        for (int i = 0; i < NITER; ++i) {
            const bool haveP = (i < NITER - 1);
            const bool haveW = (i + 2 < NITER);
            float a1 = 0.0f, a2 = 0.0f, a3 = 0.0f;
            if (haveW) {
                const float* ws = W1 + (size_t)(i + 2) * 1280;
                a1 = __ldg(ws + pt);
                a2 = __ldg(ws + 512 + pt);
                if (pt < 256) a3 = __ldg(ws + 1024 + pt);
            }
            if (i >= 1) {
                const int mi = (i - 1) & 1;
                mbar_wait(MD + 8*mi, phmd[mi] & 1); phmd[mi]++;
            }
            // warp 1: issue B copies for chunks 2i+1, 2i+2 (safe after MD(i-1))
            if (w == 1 && i >= 1) {
                if (elect_one()) {
                    const int c1 = 2*i + 1;
                    expect_tx(BF + 8*(c1 % 3), B_SLOT);
                    bulk_copy(sbase + OFF_B + (c1 % 3) * B_SLOT,
                              gsrc + (size_t)c1 * B_SLOT, B_SLOT, BF + 8*(c1 % 3));
                    const int c2 = 2*i + 2;
                    if (c2 < NCHUNK) {
                        expect_tx(BF + 8*(c2 % 3), B_SLOT);
                        bulk_copy(sbase + OFF_B + (c2 % 3) * B_SLOT,
                                  gsrc + (size_t)c2 * B_SLOT, B_SLOT, BF + 8*(c2 % 3));
                    }
                }
            }
            if (haveP) {
                const int pr2 = (i + 1) & 1;
                const char* wp = smem + OFF_W1 + pr2 * 5120;
                produce8(tmem_base, wp, qq, 2*pr2, sp, kg);
                produce8(tmem_base, wp + 2560, qq, 2*pr2 + 1, sp, kg);
                asm volatile("tcgen05.wait::st.sync.aligned;" ::: "memory");
                asm volatile("tcgen05.fence::before_thread_sync;" ::: "memory");
                if (elect_one()) mbar_arrive(AR + 8*pr2);
            }
            if (haveW) {
                char* wd = smem + OFF_W1 + (i & 1) * 5120;
                *(float*)(wd + off1) = a1;
                *(float*)(wd + off2) = a2;
                if (pt < 256) *(float*)(wd + off3) = a3;
            }
            asm volatile("bar.sync 1, 512;" ::: "memory");
        }

        // final MMA pair (iter 31 -> MD[1])
        mbar_wait(MD + 8*1, phmd[1] & 1);
        asm volatile("tcgen05.fence::after_thread_sync;" ::: "memory");

        // epilogue: D cols kg*64 .. kg*64+63, rows sp*32+lane
        {
            const int m = bm + sp * 32 + lane;
            float* orow = out + (size_t)m * NDIM + bn + kg * 64;
#pragma unroll
            for (int q = 0; q < 2; ++q) {
                uint32_t r[32];
                LDTM32(r, tmem_base + kg * 64 + q * 32);
                asm volatile("tcgen05.wait::ld.sync.aligned;" ::: "memory");
#pragma unroll
                for (int i = 0; i < 8; ++i) {
                    *(float4*)(orow + q * 32 + 4 * i) =
                        make_float4(__uint_as_float(r[4*i]), __uint_as_float(r[4*i+1]),
                                    __uint_as_float(r[4*i+2]), __uint_as_float(r[4*i+3]));
                }
            }
        }
    }

    __syncthreads();
    if (w == 0) {
        asm volatile("tcgen05.dealloc.cta_group::1.sync.aligned.b32 %0, %1;"
                     :: "r"(tmem_base), "r"(512));
    }
#endif  // TC_OK
}

// ============================================================================
// Kernel B: known-good FFMA fallback — active only WITHOUT SM103_ALL
// ============================================================================
#define FBM 128
#define FBN 128
#define FBK 16

__global__ __launch_bounds__(256)
void ffq_fused_kernel(const float* __restrict__ x,
                      const float* __restrict__ qp,
                      const float* __restrict__ W1,
                      const float* __restrict__ W2,
                      float* __restrict__ out)
{
#if !TC_OK
    __shared__ float qs[FBM][NQ];
    __shared__ float As[FBK][FBM];
    __shared__ float Bs[FBK][FBN];

    const int tid = threadIdx.x;
    const int bm  = blockIdx.y * FBM;
    const int bn  = blockIdx.x * FBN;

    if (tid < FBM) {
        const int r = bm + tid;
        float c[NQ];
#pragma unroll
        for (int j = 0; j < NQ; j++) c[j] = cosf(x[r * NQ + j] + qp[j]);
        float suf = 1.0f;
#pragma unroll
        for (int j = 1; j < NQ; j++) suf *= c[j];
        qs[tid][0] = suf;
        float pre = c[0];
#pragma unroll
        for (int j = 1; j < NQ; j++) { pre *= c[j]; qs[tid][j] = pre; }
    }
    __syncthreads();

    const int ty = tid >> 4, tx = tid & 15;
    const int a_m = tid >> 1, a_kh = (tid & 1) * 8;

    float acc[8][8];
#pragma unroll
    for (int i = 0; i < 8; i++)
#pragma unroll
        for (int j = 0; j < 8; j++) acc[i][j] = 0.0f;

    float qr[NQ];
#pragma unroll
    for (int j = 0; j < NQ; j++) qr[j] = qs[a_m][j];

    for (int kk = 0; kk < KDIM; kk += FBK) {
#pragma unroll
        for (int ki = 0; ki < 8; ki++) {
            const int k = a_kh + ki;
            const float* ww = &W1[(kk + k) * NQ];
            float s = 0.0f;
#pragma unroll
            for (int j = 0; j < NQ; j++) s += qr[j] * ww[j];
            As[k][a_m] = fmaxf(s, 0.0f);
        }
#pragma unroll
        for (int v = 0; v < 2; v++) {
            const int idx = tid + v * 256;
            const int nrow = idx >> 2, kc = (idx & 3) * 4;
            const float4 t = *(const float4*)&W2[(size_t)(bn + nrow) * KDIM + kk + kc];
            Bs[kc + 0][nrow] = t.x; Bs[kc + 1][nrow] = t.y;
            Bs[kc + 2][nrow] = t.z; Bs[kc + 3][nrow] = t.w;
        }
        __syncthreads();
#pragma unroll
        for (int k = 0; k < FBK; k++) {
            float a[8], b[8];
            const float4 a0 = *(const float4*)&As[k][ty * 8];
            const float4 a1 = *(const float4*)&As[k][ty * 8 + 4];
            const float4 b0 = *(const float4*)&Bs[k][tx * 8];
            const float4 b1 = *(const float4*)&Bs[k][tx * 8 + 4];
            a[0]=a0.x;a[1]=a0.y;a[2]=a0.z;a[3]=a0.w;a[4]=a1.x;a[5]=a1.y;a[6]=a1.z;a[7]=a1.w;
            b[0]=b0.x;b[1]=b0.y;b[2]=b0.z;b[3]=b0.w;b[4]=b1.x;b[5]=b1.y;b[6]=b1.z;b[7]=b1.w;
#pragma unroll
            for (int i = 0; i < 8; i++)
#pragma unroll
                for (int j = 0; j < 8; j++) acc[i][j] += a[i] * b[j];
        }
        __syncthreads();
    }
#pragma unroll
    for (int i = 0; i < 8; i++) {
        const int m = bm + ty * 8 + i;
        float* o = &out[(size_t)m * NDIM + bn + tx * 8];
        *(float4*)&o[0] = make_float4(acc[i][0], acc[i][1], acc[i][2], acc[i][3]);
        *(float4*)&o[4] = make_float4(acc[i][4], acc[i][5], acc[i][6], acc[i][7]);
    }
#endif  // !TC_OK
}

extern "C" void kernel_launch(void* const* d_in, const int* in_sizes, int n_in,
                              void* d_out, int out_size)
{
    const float* x  = (const float*)d_in[0];
    const float* qp = (const float*)d_in[1];
    const float* W1 = (const float*)d_in[2];
    const float* W2 = (const float*)d_in[3];
    float* out = (float*)d_out;

    const int M = in_sizes[0] / NQ;   // 16384

    cudaFuncAttributes fa; fa.numRegs = 0;
    cudaError_t qerr = cudaFuncGetAttributes(&fa, ffq_tc_kernel);
    const bool tc = (qerr == cudaSuccess) && (fa.numRegs > 32);

    if (tc || qerr != cudaSuccess) {
        convert_w2_kernel<<<(NDIM * KDIM / 8) / 256, 256>>>(W2);
        cudaFuncSetAttribute(ffq_tc_kernel, cudaFuncAttributeMaxDynamicSharedMemorySize, SMEM_BYTES);
        dim3 grid(NBLK, M / BM);      // (4, 128)
        ffq_tc_kernel<<<grid, THREADS, SMEM_BYTES>>>(x, qp, W1, out);
    }
    if (!tc) {
        dim3 gridB(NDIM / FBN, M / FBM);
        ffq_fused_kernel<<<gridB, 256>>>(x, qp, W1, W2, out);
    }
}

// round 8
// speedup vs baseline: 11.3697x; 1.1348x over previous
#include <cuda_runtime.h>
#include <cuda_fp16.h>
#include <math.h>
#include <stdint.h>

typedef unsigned long long ull;

#define NQ      10
#define KDIM    4096
#define NDIM    1024
#define BM      128
#define BN      256
#define KC      64
#define NCHUNK  64
#define NITER   16                   // quads of 4 chunks
#define THREADS 544
#define NBLK    (NDIM / BN)          // 4

#if defined(__CUDA_ARCH__) && defined(__CUDA_ARCH_HAS_FEATURE__)
#  if __CUDA_ARCH_HAS_FEATURE__(SM103_ALL) || __CUDA_ARCH_HAS_FEATURE__(SM100_ALL)
#    define TC_OK 1
#  endif
#endif
#ifndef TC_OK
#  define TC_OK 0
#endif

// SMEM layout
#define OFF_TMEM 0
#define OFF_MD   16                  // 2 x 8B mma-quad-done
#define OFF_BF   32                  // 6 x 8B b-full
#define OFF_AR   96                  // 2 x 8B a-quad-ready (count 16)
#define OFF_W1   128                 // 2 x 10240B W1 quad staging
#define OFF_B    24576               // 6 slots x 32KB fp16 tiles
#define B_SLOT   32768
#define SMEM_BYTES (OFF_B + 6 * B_SLOT)   // 221184

// idesc kind::f16: dtype=F32, a/b=FP16, M=128, N=256
#define IDESC 0x08400010u
#define SW128(o) ((o) ^ (((o) >> 3) & 0x70))

// converted W2: [nb][chunk] 32KB fp16 SW128 tile images (8MB, L2-resident)
__device__ __align__(1024) unsigned char g_w2conv[(size_t)NBLK * NCHUNK * B_SLOT];

static __device__ __forceinline__ uint32_t pack_f16(float lo, float hi) {
    uint32_t r;  // hi -> upper half, lo -> lower half
    asm("cvt.rn.f16x2.f32 %0, %1, %2;" : "=r"(r) : "f"(hi), "f"(lo));
    return r;
}

// ============================================================================
// Kernel 0: W2 fp32 -> fp16 SW128-swizzled tile images
// ============================================================================
__global__ __launch_bounds__(256)
void convert_w2_kernel(const float* __restrict__ W2)
{
    const int t   = blockIdx.x * 256 + threadIdx.x;   // 0 .. 1024*512-1
    const int row = t >> 9;
    const int k0  = (t & 511) << 3;
    const int nb  = row >> 8, n = row & 255;
    const int c   = k0 >> 6,  k = k0 & 63;

    const float4* p = (const float4*)(W2 + (size_t)row * KDIM + k0);
    const float4 u = p[0], v = p[1];
    uint32_t h0 = pack_f16(u.x, u.y);
    uint32_t h1 = pack_f16(u.z, u.w);
    uint32_t h2 = pack_f16(v.x, v.y);
    uint32_t h3 = pack_f16(v.z, v.w);

    unsigned char* base = g_w2conv + ((size_t)(nb * NCHUNK + c)) * B_SLOT;
    const uint32_t off = SW128((uint32_t)(n * 128 + k * 2));
    *(uint4*)(base + off) = make_uint4(h0, h1, h2, h3);
}

// ============================================================================
// Kernel A: warp-specialized TS-mode tcgen05 fp16 GEMM, quad pipelined
// ============================================================================
#if TC_OK
static __device__ __forceinline__ uint32_t smem_u32(const void* p) {
    uint32_t a;
    asm("{ .reg .u64 t; cvta.to.shared.u64 t, %1; cvt.u32.u64 %0, t; }" : "=r"(a) : "l"(p));
    return a;
}
static __device__ __forceinline__ bool elect_one() {
    uint32_t p;
    asm volatile("{ .reg .pred P; elect.sync _|P, 0xFFFFFFFF; selp.b32 %0, 1, 0, P; }" : "=r"(p));
    return p != 0;
}
static __device__ __forceinline__ ull make_desc(uint32_t addr) {  // SW128 K-major
    return (2ULL << 61) | (1ULL << 46) | (64ULL << 32) | (1ULL << 16) |
           (ull)((addr >> 4) & 0x3FFF);
}
static __device__ __forceinline__ ull fma2(ull a, ull b, ull c) {
    ull d;
    asm("fma.rn.f32x2 %0, %1, %2, %3;" : "=l"(d) : "l"(a), "l"(b), "l"(c));
    return d;
}
static __device__ __forceinline__ void mbar_wait(uint32_t mbar, uint32_t ph) {
    asm volatile(
        "{\n\t.reg .pred P;\n"
        "WL_%=:\n\t"
        "mbarrier.try_wait.parity.acquire.cta.shared::cta.b64 P, [%0], %1, 0x989680;\n\t"
        "@P bra WD_%=;\n\t"
        "bra WL_%=;\n"
        "WD_%=:\n\t}"
        :: "r"(mbar), "r"(ph) : "memory");
}
static __device__ __forceinline__ void mbar_arrive(uint32_t mbar) {
    asm volatile("mbarrier.arrive.shared.b64 _, [%0];" :: "r"(mbar) : "memory");
}
static __device__ __forceinline__ void mma_ts(uint32_t d, uint32_t a, ull b, uint32_t en) {
    asm volatile(
        "{\n\t.reg .pred p;\n\t"
        "setp.ne.u32 p, %5, 0;\n\t"
        "tcgen05.mma.cta_group::1.kind::f16 [%0], [%1], %2, %3, {%4,%4,%4,%4}, p;\n\t}"
        :: "r"(d), "r"(a), "l"(b), "r"(IDESC), "r"(0u), "r"(en) : "memory");
}
static __device__ __forceinline__ void bulk_copy(uint32_t dst, const void* src,
                                                 uint32_t bytes, uint32_t mbar) {
    asm volatile(
        "cp.async.bulk.shared::cluster.global.mbarrier::complete_tx::bytes [%0], [%1], %2, [%3];"
        :: "r"(dst), "l"(src), "r"(bytes), "r"(mbar) : "memory");
}
static __device__ __forceinline__ void expect_tx(uint32_t mbar, uint32_t bytes) {
    asm volatile("mbarrier.arrive.expect_tx.shared.b64 _, [%0], %1;"
                 :: "r"(mbar), "r"(bytes) : "memory");
}

#define STTM8(addr, r) asm volatile( \
    "tcgen05.st.sync.aligned.32x32b.x8.b32 [%0], {%1,%2,%3,%4,%5,%6,%7,%8};" \
    :: "r"(addr), "r"((r)[0]),"r"((r)[1]),"r"((r)[2]),"r"((r)[3]), \
       "r"((r)[4]),"r"((r)[5]),"r"((r)[6]),"r"((r)[7]) : "memory")

#define LDTM32(r, addr) asm volatile( \
    "tcgen05.ld.sync.aligned.32x32b.x32.b32 " \
    "{%0,%1,%2,%3,%4,%5,%6,%7,%8,%9,%10,%11,%12,%13,%14,%15," \
    "%16,%17,%18,%19,%20,%21,%22,%23,%24,%25,%26,%27,%28,%29,%30,%31}, [%32];" \
    : "=r"(r[0]),"=r"(r[1]),"=r"(r[2]),"=r"(r[3]),"=r"(r[4]),"=r"(r[5]),"=r"(r[6]),"=r"(r[7]), \
      "=r"(r[8]),"=r"(r[9]),"=r"(r[10]),"=r"(r[11]),"=r"(r[12]),"=r"(r[13]),"=r"(r[14]),"=r"(r[15]), \
      "=r"(r[16]),"=r"(r[17]),"=r"(r[18]),"=r"(r[19]),"=r"(r[20]),"=r"(r[21]),"=r"(r[22]),"=r"(r[23]), \
      "=r"(r[24]),"=r"(r[25]),"=r"(r[26]),"=r"(r[27]),"=r"(r[28]),"=r"(r[29]),"=r"(r[30]),"=r"(r[31]) \
    : "r"(addr))

// produce one quad (4 chunks x 16 k) of fp16 A into TMEM buffer qb
static __device__ __forceinline__ void produce_quad(
    uint32_t tmem_base, const char* w1q, const ull* qq, int qb, int sp, int kg)
{
#pragma unroll
    for (int c = 0; c < 4; ++c) {
        const ulonglong2* w1v = (const ulonglong2*)(w1q + c * 2560);
        uint32_t h[8];
#pragma unroll
        for (int i = 0; i < 8; ++i) {
            const int kp = kg * 8 + i;
            ull acc = 0ULL;
#pragma unroll
            for (int j = 0; j < 5; ++j) {
                ulonglong2 ww = w1v[kp * 5 + j];
                acc = fma2(qq[2 * j],     ww.x, acc);
                acc = fma2(qq[2 * j + 1], ww.y, acc);
            }
            float s0 = fmaxf(__uint_as_float((uint32_t)acc), 0.0f);
            float s1 = fmaxf(__uint_as_float((uint32_t)(acc >> 32)), 0.0f);
            h[i] = pack_f16(s0, s1);
        }
        const uint32_t a = tmem_base + 256 + qb * 128 + c * 32 + kg * 8 + ((uint32_t)sp << 21);
        STTM8(a, h);
    }
}

// W1 staging offset for linear element e in [0, 2560)
static __device__ __forceinline__ uint32_t w1_off(int e) {
    const int ch = e / 640, rem = e - ch * 640;
    const int k = rem / NQ, j = rem - k * NQ;
    return (uint32_t)(ch * 2560 + (k >> 1) * 80 + j * 8 + (k & 1) * 4);
}
#endif  // TC_OK

__global__ __launch_bounds__(THREADS, 1)
void ffq_tc_kernel(const float* __restrict__ x,
                   const float* __restrict__ qp,
                   const float* __restrict__ W1,
                   float* __restrict__ out)
{
#if TC_OK
    extern __shared__ char smem[];
    const uint32_t sbase = smem_u32(smem);
    const int tid = threadIdx.x;
    const int w = tid >> 5, lane = tid & 31;
    const int nb = blockIdx.x;
    const int bm = blockIdx.y * BM;
    const int bn = nb * BN;

    const uint32_t MD = sbase + OFF_MD;
    const uint32_t BF = sbase + OFF_BF;
    const uint32_t AR = sbase + OFF_AR;
    const unsigned char* gsrc = g_w2conv + (size_t)nb * NCHUNK * B_SLOT;

    if (w == 0) {
        asm volatile("tcgen05.alloc.cta_group::1.sync.aligned.shared::cta.b32 [%0], %1;"
                     :: "r"(sbase + OFF_TMEM), "r"(512) : "memory");
        asm volatile("tcgen05.relinquish_alloc_permit.cta_group::1.sync.aligned;");
        if (elect_one()) {
#pragma unroll
            for (int i = 0; i < 2; ++i) {
                asm volatile("mbarrier.init.shared.b64 [%0], %1;" :: "r"(MD + 8*i), "r"(1u)  : "memory");
                asm volatile("mbarrier.init.shared.b64 [%0], %1;" :: "r"(AR + 8*i), "r"(16u) : "memory");
            }
#pragma unroll
            for (int i = 0; i < 6; ++i)
                asm volatile("mbarrier.init.shared.b64 [%0], %1;" :: "r"(BF + 8*i), "r"(1u) : "memory");
        }
    }
    __syncthreads();

    // prologue B copies: fill all 6 slots (chunks 0..5)
    if (w == 1 && elect_one()) {
#pragma unroll
        for (int s = 0; s < 6; ++s) {
            expect_tx(BF + 8*s, B_SLOT);
            bulk_copy(sbase + OFF_B + s * B_SLOT, gsrc + (size_t)s * B_SLOT,
                      B_SLOT, BF + 8*s);
        }
    }

    uint32_t tmem_base;
    asm volatile("ld.shared.b32 %0, [%1];" : "=r"(tmem_base) : "r"(sbase + OFF_TMEM));

    if (w == 0) {
        // ===================== scheduler warp =====================
        if (elect_one()) {
            int phar[2] = {0,0}, phbf[6] = {0,0,0,0,0,0};
            for (int i = 0; i < NITER; ++i) {
                const int pr = i & 1;
                mbar_wait(AR + 8*pr, phar[pr] & 1); phar[pr]++;
                asm volatile("tcgen05.fence::after_thread_sync;" ::: "memory");
#pragma unroll
                for (int j = 0; j < 4; ++j) {
                    const int c = 4*i + j, s = c % 6;
                    mbar_wait(BF + 8*s, phbf[s] & 1); phbf[s]++;
                    const ull bH = make_desc(sbase + OFF_B + s * B_SLOT);
                    const uint32_t aB = tmem_base + 256 + pr * 128 + j * 32;
#pragma unroll
                    for (int ks = 0; ks < 4; ++ks)
                        mma_ts(tmem_base, aB + ks*8, bH + ks*2,
                               (i > 0) || (j > 0) || (ks > 0));
                }
                asm volatile("tcgen05.commit.cta_group::1.mbarrier::arrive::one.shared::cluster.b64 [%0];"
                             :: "r"(MD + 8*pr) : "memory");
            }
        }
    } else {
        // ===================== producer warps (1..16) =====================
        const int sp = w & 3;             // TMEM subpartition
        const int kg = (w - 1) >> 2;      // k-group 0..3
        const int pt = tid - 32;          // 0..511

        // analytic quantum features for row m = bm + sp*32 + lane
        ull qq[NQ];
        {
            const int m = bm + sp * 32 + lane;
            float c[NQ];
#pragma unroll
            for (int j = 0; j < NQ; j++) c[j] = cosf(x[m * NQ + j] + qp[j]);
            float suf = 1.0f;
#pragma unroll
            for (int j = 1; j < NQ; j++) suf *= c[j];
            float qv[NQ];
            qv[0] = suf;
            float pre = c[0];
#pragma unroll
            for (int j = 1; j < NQ; j++) { pre *= c[j]; qv[j] = pre; }
#pragma unroll
            for (int j = 0; j < NQ; j++) {
                uint32_t b = __float_as_uint(qv[j]);
                qq[j] = ((ull)b << 32) | (ull)b;
            }
        }

        // W1 staging: 2560 floats per quad, 512 threads x 5 elements
        uint32_t offs[5];
#pragma unroll
        for (int s = 0; s < 5; ++s) offs[s] = w1_off(pt + s * 512);

        // stage W1 quads 0 and 1
#pragma unroll
        for (int p = 0; p < 2; ++p) {
            const float* ws = W1 + (size_t)p * 2560;
            char* wd = smem + OFF_W1 + p * 10240;
#pragma unroll
            for (int s = 0; s < 5; ++s)
                *(float*)(wd + offs[s]) = ws[pt + s * 512];
        }
        asm volatile("bar.sync 1, 512;" ::: "memory");

        // produce quad 0 into buf 0
        produce_quad(tmem_base, smem + OFF_W1, qq, 0, sp, kg);
        asm volatile("tcgen05.wait::st.sync.aligned;" ::: "memory");
        asm volatile("tcgen05.fence::before_thread_sync;" ::: "memory");
        if (elect_one()) mbar_arrive(AR + 0);

        int phmd[2] = {0,0};
        int nc = 6;    // next B chunk to copy (warp 1)

        for (int i = 0; i < NITER; ++i) {
            const bool haveP = (i < NITER - 1);
            const bool haveW = (i + 2 < NITER);
            float a[5];
            if (haveW) {
                const float* ws = W1 + (size_t)(i + 2) * 2560;
#pragma unroll
                for (int s = 0; s < 5; ++s) a[s] = __ldg(ws + pt + s * 512);
            }
            if (i >= 1) {
                const int mi = (i - 1) & 1;
                mbar_wait(MD + 8*mi, phmd[mi] & 1); phmd[mi]++;
                // warp 1: issue B copies; slots of chunks <= 4(i-1)+3 are free,
                // so chunks up to 4i+5 + may be copied (c-6 <= 4i-1 <= 4(i-1)+3)
                if (w == 1 && elect_one()) {
                    const int lim = (4*i + 5 < NCHUNK - 1) ? (4*i + 5) : (NCHUNK - 1);
                    for (; nc <= lim; ++nc) {
                        const int s = nc % 6;
                        expect_tx(BF + 8*s, B_SLOT);
                        bulk_copy(sbase + OFF_B + s * B_SLOT,
                                  gsrc + (size_t)nc * B_SLOT, B_SLOT, BF + 8*s);
                    }
                }
            }
            if (haveP) {
                const int pr2 = (i + 1) & 1;
                produce_quad(tmem_base, smem + OFF_W1 + pr2 * 10240, qq, pr2, sp, kg);
                asm volatile("tcgen05.wait::st.sync.aligned;" ::: "memory");
                asm volatile("tcgen05.fence::before_thread_sync;" ::: "memory");
                if (elect_one()) mbar_arrive(AR + 8*pr2);
            }
            if (haveW) {
                char* wd = smem + OFF_W1 + (i & 1) * 10240;
#pragma unroll
                for (int s = 0; s < 5; ++s)
                    *(float*)(wd + offs[s]) = a[s];
            }
            asm volatile("bar.sync 1, 512;" ::: "memory");
        }

        // final quad (15 -> MD[1])
        mbar_wait(MD + 8*1, phmd[1] & 1);
        asm volatile("tcgen05.fence::after_thread_sync;" ::: "memory");

        // epilogue: D cols kg*64 .. kg*64+63, rows sp*32+lane
        {
            const int m = bm + sp * 32 + lane;
            float* orow = out + (size_t)m * NDIM + bn + kg * 64;
#pragma unroll
            for (int q = 0; q < 2; ++q) {
                uint32_t r[32];
                LDTM32(r, tmem_base + kg * 64 + q * 32);
                asm volatile("tcgen05.wait::ld.sync.aligned;" ::: "memory");
#pragma unroll
                for (int i = 0; i < 8; ++i) {
                    *(float4*)(orow + q * 32 + 4 * i) =
                        make_float4(__uint_as_float(r[4*i]), __uint_as_float(r[4*i+1]),
                                    __uint_as_float(r[4*i+2]), __uint_as_float(r[4*i+3]));
                }
            }
        }
    }

    __syncthreads();
    if (w == 0) {
        asm volatile("tcgen05.dealloc.cta_group::1.sync.aligned.b32 %0, %1;"
                     :: "r"(tmem_base), "r"(512));
    }
#endif  // TC_OK
}

// ============================================================================
// Kernel B: known-good FFMA fallback — active only WITHOUT SM103_ALL
// ============================================================================
#define FBM 128
#define FBN 128
#define FBK 16

__global__ __launch_bounds__(256)
void ffq_fused_kernel(const float* __restrict__ x,
                      const float* __restrict__ qp,
                      const float* __restrict__ W1,
                      const float* __restrict__ W2,
                      float* __restrict__ out)
{
#if !TC_OK
    __shared__ float qs[FBM][NQ];
    __shared__ float As[FBK][FBM];
    __shared__ float Bs[FBK][FBN];

    const int tid = threadIdx.x;
    const int bm  = blockIdx.y * FBM;
    const int bn  = blockIdx.x * FBN;

    if (tid < FBM) {
        const int r = bm + tid;
        float c[NQ];
#pragma unroll
        for (int j = 0; j < NQ; j++) c[j] = cosf(x[r * NQ + j] + qp[j]);
        float suf = 1.0f;
#pragma unroll
        for (int j = 1; j < NQ; j++) suf *= c[j];
        qs[tid][0] = suf;
        float pre = c[0];
#pragma unroll
        for (int j = 1; j < NQ; j++) { pre *= c[j]; qs[tid][j] = pre; }
    }
    __syncthreads();

    const int ty = tid >> 4, tx = tid & 15;
    const int a_m = tid >> 1, a_kh = (tid & 1) * 8;

    float acc[8][8];
#pragma unroll
    for (int i = 0; i < 8; i++)
#pragma unroll
        for (int j = 0; j < 8; j++) acc[i][j] = 0.0f;

    float qr[NQ];
#pragma unroll
    for (int j = 0; j < NQ; j++) qr[j] = qs[a_m][j];

    for (int kk = 0; kk < KDIM; kk += FBK) {
#pragma unroll
        for (int ki = 0; ki < 8; ki++) {
            const int k = a_kh + ki;
            const float* ww = &W1[(kk + k) * NQ];
            float s = 0.0f;
#pragma unroll
            for (int j = 0; j < NQ; j++) s += qr[j] * ww[j];
            As[k][a_m] = fmaxf(s, 0.0f);
        }
#pragma unroll
        for (int v = 0; v < 2; v++) {
            const int idx = tid + v * 256;
            const int nrow = idx >> 2, kc = (idx & 3) * 4;
            const float4 t = *(const float4*)&W2[(size_t)(bn + nrow) * KDIM + kk + kc];
            Bs[kc + 0][nrow] = t.x; Bs[kc + 1][nrow] = t.y;
            Bs[kc + 2][nrow] = t.z; Bs[kc + 3][nrow] = t.w;
        }
        __syncthreads();
#pragma unroll
        for (int k = 0; k < FBK; k++) {
            float a[8], b[8];
            const float4 a0 = *(const float4*)&As[k][ty * 8];
            const float4 a1 = *(const float4*)&As[k][ty * 8 + 4];
            const float4 b0 = *(const float4*)&Bs[k][tx * 8];
            const float4 b1 = *(const float4*)&Bs[k][tx * 8 + 4];
            a[0]=a0.x;a[1]=a0.y;a[2]=a0.z;a[3]=a0.w;a[4]=a1.x;a[5]=a1.y;a[6]=a1.z;a[7]=a1.w;
            b[0]=b0.x;b[1]=b0.y;b[2]=b0.z;b[3]=b0.w;b[4]=b1.x;b[5]=b1.y;b[6]=b1.z;b[7]=b1.w;
#pragma unroll
            for (int i = 0; i < 8; i++)
#pragma unroll
                for (int j = 0; j < 8; j++) acc[i][j] += a[i] * b[j];
        }
        __syncthreads();
    }
#pragma unroll
    for (int i = 0; i < 8; i++) {
        const int m = bm + ty * 8 + i;
        float* o = &out[(size_t)m * NDIM + bn + tx * 8];
        *(float4*)&o[0] = make_float4(acc[i][0], acc[i][1], acc[i][2], acc[i][3]);
        *(float4*)&o[4] = make_float4(acc[i][4], acc[i][5], acc[i][6], acc[i][7]);
    }
#endif  // !TC_OK
}

extern "C" void kernel_launch(void* const* d_in, const int* in_sizes, int n_in,
                              void* d_out, int out_size)
{
    const float* x  = (const float*)d_in[0];
    const float* qp = (const float*)d_in[1];
    const float* W1 = (const float*)d_in[2];
    const float* W2 = (const float*)d_in[3];
    float* out = (float*)d_out;

    const int M = in_sizes[0] / NQ;   // 16384

    cudaFuncAttributes fa; fa.numRegs = 0;
    cudaError_t qerr = cudaFuncGetAttributes(&fa, ffq_tc_kernel);
    const bool tc = (qerr == cudaSuccess) && (fa.numRegs > 32);

    if (tc || qerr != cudaSuccess) {
        convert_w2_kernel<<<(NDIM * KDIM / 8) / 256, 256>>>(W2);
        cudaFuncSetAttribute(ffq_tc_kernel, cudaFuncAttributeMaxDynamicSharedMemorySize, SMEM_BYTES);
        dim3 grid(NBLK, M / BM);      // (4, 128)
        ffq_tc_kernel<<<grid, THREADS, SMEM_BYTES>>>(x, qp, W1, out);
    }
    if (!tc) {
        dim3 gridB(NDIM / FBN, M / FBM);
        ffq_fused_kernel<<<gridB, 256>>>(x, qp, W1, W2, out);
    }
}